// round 1
// baseline (speedup 1.0000x reference)
#include <cuda_runtime.h>
#include <math.h>

#define B   32
#define T   512
#define XD  512
#define AD  512
#define HD  512
#define NC  97
#define LSTEP 25
#define KIN (XD + AD)   // 1024

// ---------------- device scratch (static, allocation-free) ----------------
__device__ float g_xProj[B * T * AD];       // 33.5 MB
__device__ float g_sProj[B * AD];
__device__ float g_e[B * T];
__device__ float g_ctxp[B * 8 * XD];        // context partials (8 t-chunks)
__device__ float g_inp[B * KIN];            // [emb(y_prev), context]
__device__ float g_h[B * HD];
__device__ float g_gi[B * 3 * HD];
__device__ float g_gh[B * 3 * HD];

// ---------------- h = 0 ----------------
__global__ void zero_h_kernel() {
    g_h[blockIdx.x * 512 + threadIdx.x] = 0.0f;
}

// ---------------- xProj = x @ xEmbed_w + b   [16384,512]x[512,512] ----------------
// 64x64 tile, K-tile 16, 256 threads, 4x4 microtile.
__global__ void xproj_kernel(const float* __restrict__ A,
                             const float* __restrict__ W,
                             const float* __restrict__ bias) {
    __shared__ float sA[16][64];
    __shared__ float sB[16][64];
    const int tx = threadIdx.x & 15;
    const int ty = threadIdx.x >> 4;
    const int m0 = blockIdx.y * 64;
    const int n0 = blockIdx.x * 64;

    float acc[4][4] = {};

    const int arow = threadIdx.x >> 2;
    const int aq   = (threadIdx.x & 3) * 4;
    const int bk   = threadIdx.x >> 4;
    const int bn   = (threadIdx.x & 15) * 4;

    for (int k0 = 0; k0 < 512; k0 += 16) {
        float4 av = *(const float4*)(A + (size_t)(m0 + arow) * 512 + k0 + aq);
        float4 bv = *(const float4*)(W + (size_t)(k0 + bk) * 512 + n0 + bn);
        __syncthreads();
        sA[aq + 0][arow] = av.x;
        sA[aq + 1][arow] = av.y;
        sA[aq + 2][arow] = av.z;
        sA[aq + 3][arow] = av.w;
        *(float4*)&sB[bk][bn] = bv;
        __syncthreads();
#pragma unroll
        for (int kk = 0; kk < 16; kk++) {
            float a0 = sA[kk][ty * 4 + 0];
            float a1 = sA[kk][ty * 4 + 1];
            float a2 = sA[kk][ty * 4 + 2];
            float a3 = sA[kk][ty * 4 + 3];
            float b0 = sB[kk][tx * 4 + 0];
            float b1 = sB[kk][tx * 4 + 1];
            float b2 = sB[kk][tx * 4 + 2];
            float b3 = sB[kk][tx * 4 + 3];
            acc[0][0] += a0 * b0; acc[0][1] += a0 * b1; acc[0][2] += a0 * b2; acc[0][3] += a0 * b3;
            acc[1][0] += a1 * b0; acc[1][1] += a1 * b1; acc[1][2] += a1 * b2; acc[1][3] += a1 * b3;
            acc[2][0] += a2 * b0; acc[2][1] += a2 * b1; acc[2][2] += a2 * b2; acc[2][3] += a2 * b3;
            acc[3][0] += a3 * b0; acc[3][1] += a3 * b1; acc[3][2] += a3 * b2; acc[3][3] += a3 * b3;
        }
    }
#pragma unroll
    for (int i = 0; i < 4; i++) {
        int m = m0 + ty * 4 + i;
#pragma unroll
        for (int j = 0; j < 4; j++) {
            int n = n0 + tx * 4 + j;
            g_xProj[(size_t)m * 512 + n] = acc[i][j] + bias[n];
        }
    }
}

// ---------------- sProj = h @ sEmbed_w + b   [32,512]x[512,512] ----------------
// grid 16 (a-chunks of 32), block 256 = 32 a-lanes x 8 b-groups (4 b each).
__global__ void sproj_kernel(const float* __restrict__ sw,
                             const float* __restrict__ sb) {
    const int a  = blockIdx.x * 32 + (threadIdx.x & 31);
    const int bg = (threadIdx.x >> 5) * 4;
    __shared__ float s_h[32][128];

    float acc0 = 0.f, acc1 = 0.f, acc2 = 0.f, acc3 = 0.f;
    for (int k0 = 0; k0 < 512; k0 += 128) {
        __syncthreads();
        for (int idx = threadIdx.x; idx < 32 * 128; idx += 256) {
            int bb = idx >> 7, kk = idx & 127;
            s_h[bb][kk] = g_h[bb * 512 + k0 + kk];
        }
        __syncthreads();
#pragma unroll 4
        for (int k = 0; k < 128; k++) {
            float wv = sw[(size_t)(k0 + k) * 512 + a];
            acc0 += wv * s_h[bg + 0][k];
            acc1 += wv * s_h[bg + 1][k];
            acc2 += wv * s_h[bg + 2][k];
            acc3 += wv * s_h[bg + 3][k];
        }
    }
    float bias = sb[a];
    g_sProj[(bg + 0) * 512 + a] = acc0 + bias;
    g_sProj[(bg + 1) * 512 + a] = acc1 + bias;
    g_sProj[(bg + 2) * 512 + a] = acc2 + bias;
    g_sProj[(bg + 3) * 512 + a] = acc3 + bias;
}

// ---------------- e[b,t] = sum_a tanh(xProj + sProj) * w[a] ----------------
// grid (16 t-chunks, 32 b), block 256 (8 warps, 4 t each).
__global__ void e_kernel(const float* __restrict__ wvec) {
    const int b  = blockIdx.y;
    const int t0 = blockIdx.x * 32;
    __shared__ __align__(16) float s_s[512];
    __shared__ __align__(16) float s_w[512];
    for (int i = threadIdx.x; i < 512; i += 256) {
        s_s[i] = g_sProj[b * 512 + i];
        s_w[i] = wvec[i];
    }
    __syncthreads();
    const int warp = threadIdx.x >> 5;
    const int lane = threadIdx.x & 31;
    for (int tt = warp; tt < 32; tt += 8) {
        const int t = t0 + tt;
        const float4* xp = (const float4*)(g_xProj + (size_t)(b * 512 + t) * 512);
        float acc = 0.f;
#pragma unroll
        for (int it = 0; it < 4; it++) {
            float4 v  = xp[it * 32 + lane];
            float4 s  = ((const float4*)s_s)[it * 32 + lane];
            float4 ww = ((const float4*)s_w)[it * 32 + lane];
            acc += tanhf(v.x + s.x) * ww.x;
            acc += tanhf(v.y + s.y) * ww.y;
            acc += tanhf(v.z + s.z) * ww.z;
            acc += tanhf(v.w + s.w) * ww.w;
        }
#pragma unroll
        for (int off = 16; off; off >>= 1) acc += __shfl_xor_sync(0xffffffffu, acc, off);
        if (lane == 0) g_e[b * 512 + t] = acc;
    }
}

// ---------------- softmax over t (per b) + context partials ----------------
// grid (8 t-chunks, 32 b), block 512. Each block recomputes softmax stats (cheap),
// then accumulates its 64-t slice of context into g_ctxp.
__global__ void smctx_kernel(const float* __restrict__ x) {
    const int b  = blockIdx.y;
    const int c  = blockIdx.x;
    const int t0 = c * 64;
    const int tid = threadIdx.x;
    __shared__ float s_red[512];
    __shared__ float s_alpha[64];

    float v = g_e[b * 512 + tid];
    s_red[tid] = v;
    __syncthreads();
    for (int s = 256; s; s >>= 1) {
        if (tid < s) s_red[tid] = fmaxf(s_red[tid], s_red[tid + s]);
        __syncthreads();
    }
    const float mx = s_red[0];
    __syncthreads();
    s_red[tid] = __expf(v - mx);
    __syncthreads();
    for (int s = 256; s; s >>= 1) {
        if (tid < s) s_red[tid] += s_red[tid + s];
        __syncthreads();
    }
    const float inv = 1.0f / s_red[0];
    if (tid < 64) s_alpha[tid] = __expf(g_e[b * 512 + t0 + tid] - mx) * inv;
    __syncthreads();

    float acc = 0.f;
    const float* xb = x + ((size_t)b * 512 + t0) * 512 + tid;
#pragma unroll 8
    for (int i = 0; i < 64; i++) acc += s_alpha[i] * xb[(size_t)i * 512];
    g_ctxp[(b * 8 + c) * 512 + tid] = acc;
}

// ---------------- build inp = [emb(y_prev), sum(ctx partials)] ----------------
__global__ void binp_kernel(const int* __restrict__ targets,
                            const float* __restrict__ emb, int step) {
    const int b = blockIdx.x, d = threadIdx.x;
    const int y = (step == 0) ? NC : targets[b * LSTEP + step - 1];
    g_inp[b * KIN + d] = emb[y * 512 + d];
    float s = 0.f;
#pragma unroll
    for (int c = 0; c < 8; c++) s += g_ctxp[(b * 8 + c) * 512 + d];
    g_inp[b * KIN + 512 + d] = s;
}

// ---------------- gi = inp @ Wih^T + bih ; gh = h @ Whh^T + bhh ----------------
// grid 96 (48 gi-chunks + 48 gh-chunks of 32 outputs), block 1024 = 32 o x 32 b.
__global__ void gru_gemm_kernel(const float* __restrict__ wih,
                                const float* __restrict__ whh,
                                const float* __restrict__ bih,
                                const float* __restrict__ bhh) {
    const bool is_gi = blockIdx.x < 48;
    const int o = (is_gi ? blockIdx.x : blockIdx.x - 48) * 32 + (threadIdx.x >> 5);
    const int b = threadIdx.x & 31;
    const float* __restrict__ in = is_gi ? g_inp : g_h;
    const float* __restrict__ wm = is_gi ? wih : whh;
    const int K = is_gi ? KIN : HD;
    __shared__ float s_in[128][33];
    const float* wrow = wm + (size_t)o * K;
    float acc = 0.f;
    for (int k0 = 0; k0 < K; k0 += 128) {
        for (int idx = threadIdx.x; idx < 32 * 128; idx += 1024) {
            int bb = idx >> 7, kk = idx & 127;
            s_in[kk][bb] = in[bb * K + k0 + kk];
        }
        __syncthreads();
#pragma unroll
        for (int k = 0; k < 128; k += 4) {
            float4 wv = *(const float4*)(wrow + k0 + k);
            acc += s_in[k + 0][b] * wv.x;
            acc += s_in[k + 1][b] * wv.y;
            acc += s_in[k + 2][b] * wv.z;
            acc += s_in[k + 3][b] * wv.w;
        }
        __syncthreads();
    }
    if (is_gi) g_gi[b * 1536 + o] = acc + bih[o];
    else       g_gh[b * 1536 + o] = acc + bhh[o];
}

// ---------------- gates + h update + fc ----------------
__global__ void gates_kernel(const float* __restrict__ fc_w,
                             const float* __restrict__ fc_b,
                             float* __restrict__ out, int step) {
    const int b = blockIdx.x, j = threadIdx.x;
    __shared__ __align__(16) float s_h[512];
    const float gir = g_gi[b * 1536 + j];
    const float giz = g_gi[b * 1536 + 512 + j];
    const float gin = g_gi[b * 1536 + 1024 + j];
    const float ghr = g_gh[b * 1536 + j];
    const float ghz = g_gh[b * 1536 + 512 + j];
    const float ghn = g_gh[b * 1536 + 1024 + j];
    const float r = 1.0f / (1.0f + __expf(-(gir + ghr)));
    const float z = 1.0f / (1.0f + __expf(-(giz + ghz)));
    const float n = tanhf(gin + r * ghn);
    const float h_old = g_h[b * 512 + j];
    const float hn = (1.0f - z) * n + z * h_old;
    g_h[b * 512 + j] = hn;
    s_h[j] = hn;
    __syncthreads();
    if (j < NC) {
        float acc = fc_b[j];
        const float4* wr = (const float4*)(fc_w + j * 512);
        const float4* hh = (const float4*)s_h;
#pragma unroll 8
        for (int k = 0; k < 128; k++) {
            float4 w4 = wr[k];
            float4 h4 = hh[k];
            acc += w4.x * h4.x + w4.y * h4.y + w4.z * h4.z + w4.w * h4.w;
        }
        out[(b * LSTEP + step) * NC + j] = acc;
    }
}

// ---------------- launch ----------------
extern "C" void kernel_launch(void* const* d_in, const int* in_sizes, int n_in,
                              void* d_out, int out_size) {
    const float* x        = (const float*)d_in[0];
    const int*   targets  = (const int*)  d_in[1];
    const float* xEmbed_w = (const float*)d_in[2];
    const float* xEmbed_b = (const float*)d_in[3];
    const float* sEmbed_w = (const float*)d_in[4];
    const float* sEmbed_b = (const float*)d_in[5];
    const float* wEmbed_w = (const float*)d_in[6];
    // d_in[7] = wEmbed_b : constant shift inside softmax -> no-op, skipped
    const float* emb      = (const float*)d_in[8];
    const float* gru_wih  = (const float*)d_in[9];
    const float* gru_whh  = (const float*)d_in[10];
    const float* gru_bih  = (const float*)d_in[11];
    const float* gru_bhh  = (const float*)d_in[12];
    const float* fc_w     = (const float*)d_in[13];
    const float* fc_b     = (const float*)d_in[14];
    float* out = (float*)d_out;

    zero_h_kernel<<<32, 512>>>();
    xproj_kernel<<<dim3(8, 256), 256>>>(x, xEmbed_w, xEmbed_b);

    for (int step = 0; step < LSTEP; step++) {
        sproj_kernel<<<16, 256>>>(sEmbed_w, sEmbed_b);
        e_kernel<<<dim3(16, 32), 256>>>(wEmbed_w);
        smctx_kernel<<<dim3(8, 32), 512>>>(x);
        binp_kernel<<<32, 512>>>(targets, emb, step);
        gru_gemm_kernel<<<96, 1024>>>(gru_wih, gru_whh, gru_bih, gru_bhh);
        gates_kernel<<<32, 512>>>(fc_w, fc_b, out, step);
    }
}

// round 2
// speedup vs baseline: 2.2147x; 2.2147x over previous
#include <cuda_runtime.h>
#include <cuda_bf16.h>
#include <math.h>

#define B   32
#define T   512
#define XD  512
#define AD  512
#define HD  512
#define NC  97
#define LSTEP 25

// ---------------- device scratch (static, allocation-free) ----------------
__device__ __nv_bfloat16 g_xProjh[B * T * AD];     // 16.8 MB (bf16)
__device__ float g_Wcat[512 * 2048];               // [k][ sEmbed_w(512) | Whh^T(1536) ]
__device__ float g_Wet[512 * 1536];                // Wih_emb^T   [k][o]
__device__ float g_Wct[512 * 1536];                // Wih_ctx^T   [k][o]
__device__ float g_embSeq[LSTEP * B * 512];        // gathered embeddings for all steps
__device__ float g_giemb[LSTEP * B * 1536];        // precomputed gi (emb part) + bih
__device__ float g_hT[512 * 32];                   // h transposed [k][b]
__device__ float g_hp[4][32][2048];                // h-GEMM partials (4 K-splits)
__device__ float g_cp[4][32][1536];                // ctx-GEMM partials
__device__ float g_e[B * T];
__device__ float g_ctxp_t[8 * 512 * 32];           // ctx partials transposed [(c*512+d)*32+b]

// ---------------- init: h = 0 ----------------
__global__ void init_kernel() {
    g_hT[blockIdx.x * 512 + threadIdx.x] = 0.0f;
}

// ---------------- one-time weight repack ----------------
__global__ void repack_kernel(const float* __restrict__ sw,
                              const float* __restrict__ wih,
                              const float* __restrict__ whh) {
    int i = blockIdx.x * blockDim.x + threadIdx.x;
    if (i < 512 * 2048) {
        int k = i >> 11, j = i & 2047;
        g_Wcat[i] = (j < 512) ? sw[k * 512 + j] : whh[(j - 512) * 512 + k];
    }
    if (i < 512 * 1536) {
        int k = i / 1536, o = i - k * 1536;
        g_Wet[i] = wih[o * 1024 + k];
        g_Wct[i] = wih[o * 1024 + 512 + k];
    }
}

// ---------------- gather teacher-forced embedding sequence ----------------
__global__ void embseq_kernel(const int* __restrict__ targets,
                              const float* __restrict__ emb) {
    const int s = blockIdx.x, b = blockIdx.y;
    const int y = (s == 0) ? NC : targets[b * LSTEP + s - 1];
    g_embSeq[(s * 32 + b) * 512 + threadIdx.x] = emb[y * 512 + threadIdx.x];
}

// ---------------- 128x128 SGEMM, 8x8 microtile, reg prefetch ----------------
// C[M,N] = A[M,K] @ W[K,N] + bias ; N % 128 == 0, K % 8 == 0, M guarded.
template<bool BF16OUT>
__global__ void sgemm128(const float* __restrict__ A, const float* __restrict__ W,
                         const float* __restrict__ bias, float* __restrict__ outF,
                         __nv_bfloat16* __restrict__ outH, int M, int N, int K) {
    __shared__ float sA[8][128];
    __shared__ float sB[8][128];
    const int m0 = blockIdx.y * 128;
    const int n0 = blockIdx.x * 128;
    const int tid = threadIdx.x;                 // 256 threads
    const int arow = tid >> 1, akq = (tid & 1) * 4;
    const int bk = tid >> 5, bn = (tid & 31) * 4;
    const int tx = tid & 15, ty = tid >> 4;

    int aRowG = m0 + arow; if (aRowG >= M) aRowG = M - 1;

    float4 av = *(const float4*)(A + (size_t)aRowG * K + akq);
    float4 bv = *(const float4*)(W + (size_t)bk * N + n0 + bn);

    float acc[8][8];
#pragma unroll
    for (int i = 0; i < 8; i++)
#pragma unroll
        for (int j = 0; j < 8; j++) acc[i][j] = 0.0f;

    for (int k0 = 0; k0 < K; k0 += 8) {
        __syncthreads();
        sA[akq + 0][arow] = av.x;
        sA[akq + 1][arow] = av.y;
        sA[akq + 2][arow] = av.z;
        sA[akq + 3][arow] = av.w;
        *(float4*)&sB[bk][bn] = bv;
        __syncthreads();
        if (k0 + 8 < K) {
            av = *(const float4*)(A + (size_t)aRowG * K + k0 + 8 + akq);
            bv = *(const float4*)(W + (size_t)(k0 + 8 + bk) * N + n0 + bn);
        }
#pragma unroll
        for (int kk = 0; kk < 8; kk++) {
            float ar[8], br[8];
            *(float4*)&ar[0] = *(const float4*)&sA[kk][ty * 8];
            *(float4*)&ar[4] = *(const float4*)&sA[kk][ty * 8 + 4];
            *(float4*)&br[0] = *(const float4*)&sB[kk][tx * 8];
            *(float4*)&br[4] = *(const float4*)&sB[kk][tx * 8 + 4];
#pragma unroll
            for (int i = 0; i < 8; i++)
#pragma unroll
                for (int j = 0; j < 8; j++)
                    acc[i][j] += ar[i] * br[j];
        }
    }

#pragma unroll
    for (int i = 0; i < 8; i++) {
        int m = m0 + ty * 8 + i;
        if (m >= M) break;
        if (BF16OUT) {
#pragma unroll
            for (int j = 0; j < 8; j += 2) {
                int n = n0 + tx * 8 + j;
                __nv_bfloat162 h2 = __floats2bfloat162_rn(acc[i][j] + bias[n],
                                                          acc[i][j + 1] + bias[n + 1]);
                *(__nv_bfloat162*)(outH + (size_t)m * N + n) = h2;
            }
        } else {
#pragma unroll
            for (int j = 0; j < 8; j++) {
                int n = n0 + tx * 8 + j;
                outF[(size_t)m * N + n] = acc[i][j] + bias[n];
            }
        }
    }
}

// ---------------- h-GEMM: [sProj | gh](partials) = h @ Wcat ----------------
// grid 128 = 32 col-tiles x 4 K-splits, block 512 (16 warps x 4 cols, lane=b).
__global__ void hgemm_kernel() {
    const int ks = blockIdx.x >> 5;
    const int ct = blockIdx.x & 31;
    const int k0 = ks * 128;
    const int warp = threadIdx.x >> 5;
    const int lane = threadIdx.x & 31;
    const int c = ct * 64 + warp * 4;
    __shared__ float s_h[128 * 32];
    for (int i = threadIdx.x; i < 128 * 32; i += 512)
        s_h[i] = g_hT[k0 * 32 + i];
    __syncthreads();
    float4 acc = make_float4(0.f, 0.f, 0.f, 0.f);
#pragma unroll 8
    for (int kk = 0; kk < 128; kk++) {
        float hv = s_h[kk * 32 + lane];
        float4 wv = *(const float4*)&g_Wcat[(size_t)(k0 + kk) * 2048 + c];
        acc.x += hv * wv.x; acc.y += hv * wv.y;
        acc.z += hv * wv.z; acc.w += hv * wv.w;
    }
    *(float4*)&g_hp[ks][lane][c] = acc;
}

// ---------------- e[b,t] = sum_a tanh(xProj + sProj) * w[a] ----------------
__global__ void e_kernel(const float* __restrict__ sb, const float* __restrict__ wvec) {
    const int b  = blockIdx.y;
    const int t0 = blockIdx.x * 32;
    __shared__ float s_s[512];
    __shared__ float s_w[512];
    for (int i = threadIdx.x; i < 512; i += 256) {
        float s = sb[i];
#pragma unroll
        for (int ks = 0; ks < 4; ks++) s += g_hp[ks][b][i];
        s_s[i] = s;
        s_w[i] = wvec[i];
    }
    __syncthreads();
    const int warp = threadIdx.x >> 5;
    const int lane = threadIdx.x & 31;
    for (int tt = warp; tt < 32; tt += 8) {
        const int t = t0 + tt;
        const uint4* xp = (const uint4*)(g_xProjh + ((size_t)(b * 512 + t)) * 512);
        float acc = 0.f;
#pragma unroll
        for (int it = 0; it < 2; it++) {
            uint4 u = xp[it * 32 + lane];
            const int base = (it * 32 + lane) * 8;
            const unsigned int uu[4] = {u.x, u.y, u.z, u.w};
#pragma unroll
            for (int q = 0; q < 4; q++) {
                float2 v = __bfloat1622float2(*(const __nv_bfloat162*)&uu[q]);
                float a0 = v.x + s_s[base + q * 2];
                float a1 = v.y + s_s[base + q * 2 + 1];
                float t0e = __expf(2.0f * a0);
                float t1e = __expf(2.0f * a1);
                float th0 = 1.0f - __fdividef(2.0f, t0e + 1.0f);
                float th1 = 1.0f - __fdividef(2.0f, t1e + 1.0f);
                acc += th0 * s_w[base + q * 2] + th1 * s_w[base + q * 2 + 1];
            }
        }
#pragma unroll
        for (int off = 16; off; off >>= 1) acc += __shfl_xor_sync(0xffffffffu, acc, off);
        if (lane == 0) g_e[b * 512 + t] = acc;
    }
}

// ---------------- softmax over t + context partials (transposed out) ----------------
__global__ void smctx_kernel(const float* __restrict__ x) {
    const int b  = blockIdx.y;
    const int c  = blockIdx.x;       // 0..7
    const int t0 = c * 64;
    const int tid = threadIdx.x;     // 512
    __shared__ float s_red[512];
    __shared__ float s_alpha[64];

    float v = g_e[b * 512 + tid];
    s_red[tid] = v;
    __syncthreads();
    for (int s = 256; s; s >>= 1) {
        if (tid < s) s_red[tid] = fmaxf(s_red[tid], s_red[tid + s]);
        __syncthreads();
    }
    const float mx = s_red[0];
    __syncthreads();
    s_red[tid] = __expf(v - mx);
    __syncthreads();
    for (int s = 256; s; s >>= 1) {
        if (tid < s) s_red[tid] += s_red[tid + s];
        __syncthreads();
    }
    const float inv = 1.0f / s_red[0];
    if (tid < 64) s_alpha[tid] = __expf(g_e[b * 512 + t0 + tid] - mx) * inv;
    __syncthreads();

    float acc = 0.f;
    const float* xb = x + ((size_t)b * 512 + t0) * 512 + tid;
#pragma unroll 8
    for (int i = 0; i < 64; i++) acc += s_alpha[i] * xb[(size_t)i * 512];
    g_ctxp_t[(c * 512 + tid) * 32 + b] = acc;
}

// ---------------- ctx-GEMM: gi_ctx(partials) = ctx @ Wct ----------------
// grid (24 col-tiles, 4 K-splits), block 512. Pre-phase reduces the 8 ctx partials.
__global__ void ctxgemm_kernel() {
    const int ct = blockIdx.x;
    const int ks = blockIdx.y;
    const int k0 = ks * 128;
    const int warp = threadIdx.x >> 5;
    const int lane = threadIdx.x & 31;
    const int c = ct * 64 + warp * 4;
    __shared__ float s_h[128 * 32];
    for (int i = threadIdx.x; i < 128 * 32; i += 512) {
        float s = 0.f;
#pragma unroll
        for (int c8 = 0; c8 < 8; c8++) s += g_ctxp_t[c8 * 512 * 32 + k0 * 32 + i];
        s_h[i] = s;
    }
    __syncthreads();
    float4 acc = make_float4(0.f, 0.f, 0.f, 0.f);
#pragma unroll 8
    for (int kk = 0; kk < 128; kk++) {
        float hv = s_h[kk * 32 + lane];
        float4 wv = *(const float4*)&g_Wct[(size_t)(k0 + kk) * 1536 + c];
        acc.x += hv * wv.x; acc.y += hv * wv.y;
        acc.z += hv * wv.z; acc.w += hv * wv.w;
    }
    *(float4*)&g_cp[ks][lane][c] = acc;
}

// ---------------- gates + h update + fc ----------------
__global__ void gates_kernel(const float* __restrict__ fc_w,
                             const float* __restrict__ fc_b,
                             const float* __restrict__ bhh,
                             float* __restrict__ out, int step) {
    const int b = blockIdx.x, j = threadIdx.x;
    __shared__ __align__(16) float s_h[512];

    float ghr = bhh[j], ghz = bhh[512 + j], ghn = bhh[1024 + j];
#pragma unroll
    for (int ks = 0; ks < 4; ks++) {
        ghr += g_hp[ks][b][512 + j];
        ghz += g_hp[ks][b][1024 + j];
        ghn += g_hp[ks][b][1536 + j];
    }
    const float* ge = g_giemb + ((size_t)step * 32 + b) * 1536;
    float gir = ge[j], giz = ge[512 + j], gin = ge[1024 + j];
#pragma unroll
    for (int ks = 0; ks < 4; ks++) {
        gir += g_cp[ks][b][j];
        giz += g_cp[ks][b][512 + j];
        gin += g_cp[ks][b][1024 + j];
    }
    const float r = 1.0f / (1.0f + __expf(-(gir + ghr)));
    const float z = 1.0f / (1.0f + __expf(-(giz + ghz)));
    const float a = gin + r * ghn;
    const float te = __expf(2.0f * a);
    const float n = 1.0f - __fdividef(2.0f, te + 1.0f);
    const float h_old = g_hT[j * 32 + b];
    const float hn = (1.0f - z) * n + z * h_old;
    g_hT[j * 32 + b] = hn;
    s_h[j] = hn;
    __syncthreads();
    if (j < NC) {
        float acc = fc_b[j];
        const float4* wr = (const float4*)(fc_w + j * 512);
        const float4* hh = (const float4*)s_h;
#pragma unroll 8
        for (int k = 0; k < 128; k++) {
            float4 w4 = wr[k];
            float4 h4 = hh[k];
            acc += w4.x * h4.x + w4.y * h4.y + w4.z * h4.z + w4.w * h4.w;
        }
        out[(b * LSTEP + step) * NC + j] = acc;
    }
}

// ---------------- launch ----------------
extern "C" void kernel_launch(void* const* d_in, const int* in_sizes, int n_in,
                              void* d_out, int out_size) {
    const float* x        = (const float*)d_in[0];
    const int*   targets  = (const int*)  d_in[1];
    const float* xEmbed_w = (const float*)d_in[2];
    const float* xEmbed_b = (const float*)d_in[3];
    const float* sEmbed_w = (const float*)d_in[4];
    const float* sEmbed_b = (const float*)d_in[5];
    const float* wEmbed_w = (const float*)d_in[6];
    // d_in[7] = wEmbed_b : constant shift inside softmax -> no-op
    const float* emb      = (const float*)d_in[8];
    const float* gru_wih  = (const float*)d_in[9];
    const float* gru_whh  = (const float*)d_in[10];
    const float* gru_bih  = (const float*)d_in[11];
    const float* gru_bhh  = (const float*)d_in[12];
    const float* fc_w     = (const float*)d_in[13];
    const float* fc_b     = (const float*)d_in[14];
    float* out = (float*)d_out;

    void *p_embSeq, *p_Wet, *p_giemb, *p_xProjh;
    cudaGetSymbolAddress(&p_embSeq, g_embSeq);
    cudaGetSymbolAddress(&p_Wet, g_Wet);
    cudaGetSymbolAddress(&p_giemb, g_giemb);
    cudaGetSymbolAddress(&p_xProjh, g_xProjh);

    init_kernel<<<32, 512>>>();
    repack_kernel<<<4096, 256>>>(sEmbed_w, gru_wih, gru_whh);
    embseq_kernel<<<dim3(LSTEP, 32), 512>>>(targets, emb);
    // gi_emb = embSeq @ Wih_emb^T + bih   [800 x 1536], K=512
    sgemm128<false><<<dim3(12, 7), 256>>>((const float*)p_embSeq, (const float*)p_Wet,
                                          gru_bih, (float*)p_giemb, nullptr,
                                          LSTEP * 32, 1536, 512);
    // xProj(bf16) = x @ xEmbed_w + b     [16384 x 512], K=512
    sgemm128<true><<<dim3(4, 128), 256>>>(x, xEmbed_w, xEmbed_b, nullptr,
                                          (__nv_bfloat16*)p_xProjh,
                                          B * T, 512, 512);

    for (int step = 0; step < LSTEP; step++) {
        hgemm_kernel<<<128, 512>>>();
        e_kernel<<<dim3(16, 32), 256>>>(sEmbed_b, wEmbed_w);
        smctx_kernel<<<dim3(8, 32), 512>>>(x);
        ctxgemm_kernel<<<dim3(24, 4), 512>>>();
        gates_kernel<<<32, 512>>>(fc_w, fc_b, gru_bhh, out, step);
    }
}

// round 7
// speedup vs baseline: 2.5023x; 1.1299x over previous
#include <cuda_runtime.h>
#include <cuda_bf16.h>
#include <cstdint>
#include <math.h>

#define B   32
#define T   512
#define XD  512
#define AD  512
#define HD  512
#define NC  97
#define LSTEP 25

// ---------------- device scratch (static, allocation-free) ----------------
__device__ __nv_bfloat16 g_xProjh[B * T * AD];     // bf16 xProj (16.8 MB)
__device__ float g_wxT[512 * 512];                 // xEmbed_w^T  [n][k] fp32
__device__ float g_weT[1536 * 512];                // Wih_emb     [o][k] fp32
__device__ float g_embS[LSTEP * B * 512];          // teacher-forced embeddings fp32
__device__ float g_Wcat[512 * 2048];               // [k][ sEmbed_w(512) | Whh^T(1536) ]
__device__ float g_Wct[512 * 1536];                // Wih_ctx^T   [k][o]
__device__ float g_giemb[LSTEP * B * 1536];        // gi (emb part) + bih
__device__ float g_hT[512 * 32];                   // h transposed [k][b]
__device__ float g_hp[4][32][2048];                // h-GEMM partials
__device__ float g_cp[4][32][1536];                // ctx-GEMM partials
__device__ float g_e[B * T];
__device__ float g_ctxp_t[8 * 512 * 32];           // ctx partials transposed

// ---------------- init: h = 0 ----------------
__global__ void init_kernel() {
    g_hT[blockIdx.x * 512 + threadIdx.x] = 0.0f;
}

// ---------------- one-time repacks ----------------
__global__ void repack_kernel(const float* __restrict__ sw,
                              const float* __restrict__ wih,
                              const float* __restrict__ whh) {
    int i = blockIdx.x * blockDim.x + threadIdx.x;
    if (i < 512 * 2048) {
        int k = i >> 11, j = i & 2047;
        g_Wcat[i] = (j < 512) ? sw[k * 512 + j] : whh[(j - 512) * 512 + k];
    }
    if (i < 512 * 1536) {
        int k = i / 1536, o = i - k * 1536;
        g_Wct[i] = wih[o * 1024 + 512 + k];
    }
}

__global__ void wpackx_kernel(const float* __restrict__ w) {
    int k = blockIdx.x, n = threadIdx.x;
    g_wxT[n * 512 + k] = w[k * 512 + n];
}

__global__ void wpacke_kernel(const float* __restrict__ wih) {
    int o = blockIdx.x, k = threadIdx.x;
    g_weT[o * 512 + k] = wih[o * 1024 + k];
}

__global__ void embseq_kernel(const int* __restrict__ targets,
                              const float* __restrict__ emb) {
    const int s = blockIdx.x, b = blockIdx.y;
    const int y = (s == 0) ? NC : targets[b * LSTEP + s - 1];
    g_embS[(s * 32 + b) * 512 + threadIdx.x] = emb[y * 512 + threadIdx.x];
}

// ---------------- TF32 warp-MMA GEMM: D[M,N] = A[M,K] @ Bt[N,K]^T + bias ----------------
// CTA tile 128x128, 8 warps (2x4), warp tile 64x32, K-chunk 32, reg prefetch.
__device__ __forceinline__ uint32_t f2tf32(float v) {
    uint32_t t;
    asm("cvt.rna.tf32.f32 %0, %1;" : "=r"(t) : "f"(v));
    return t;
}

__device__ __forceinline__ void mma_tf32(float* d, const uint32_t* a, const uint32_t* b) {
    asm volatile(
        "mma.sync.aligned.m16n8k8.row.col.f32.tf32.tf32.f32 "
        "{%0,%1,%2,%3}, {%4,%5,%6,%7}, {%8,%9}, {%0,%1,%2,%3};"
        : "+f"(d[0]), "+f"(d[1]), "+f"(d[2]), "+f"(d[3])
        : "r"(a[0]), "r"(a[1]), "r"(a[2]), "r"(a[3]), "r"(b[0]), "r"(b[1]));
}

template<bool BF16OUT>
__global__ __launch_bounds__(256)
void mm_tf32(const float* __restrict__ A,
             const float* __restrict__ Bt,
             const float* __restrict__ bias,
             float* __restrict__ outF, __nv_bfloat16* __restrict__ outH,
             int M, int N, int K) {
    __shared__ uint32_t sA[128][36];   // stride 36: conflict-free fragment loads
    __shared__ uint32_t sB[128][36];
    const int tid  = threadIdx.x;
    const int warp = tid >> 5;
    const int lane = tid & 31;
    const int wm = warp >> 2;          // 0..1
    const int wn = warp & 3;           // 0..3
    const int lr = lane >> 2;          // groupID 0..7
    const int lc = lane & 3;           // threadInGroup 0..3
    const int m0 = blockIdx.y * 128;
    const int n0 = blockIdx.x * 128;

    float acc[4][4][4];
#pragma unroll
    for (int i = 0; i < 4; i++)
#pragma unroll
        for (int j = 0; j < 4; j++)
#pragma unroll
            for (int q = 0; q < 4; q++) acc[i][j][q] = 0.0f;

    // gmem prefetch: 4 float4 per matrix per thread (128x32 fp32 tile)
    int rowS[4], qS[4], gmA[4];
#pragma unroll
    for (int s = 0; s < 4; s++) {
        int linear = tid + s * 256;
        rowS[s] = linear >> 3;
        qS[s]   = (linear & 7) * 4;
        int gm = m0 + rowS[s]; if (gm >= M) gm = M - 1;
        gmA[s] = gm;
    }
    float4 pa[4], pb[4];
#pragma unroll
    for (int s = 0; s < 4; s++) {
        pa[s] = *(const float4*)(A  + (size_t)gmA[s] * K + qS[s]);
        pb[s] = *(const float4*)(Bt + (size_t)(n0 + rowS[s]) * K + qS[s]);
    }

    for (int k0 = 0; k0 < K; k0 += 32) {
        __syncthreads();
#pragma unroll
        for (int s = 0; s < 4; s++) {
            uint32_t* da = &sA[rowS[s]][qS[s]];
            da[0] = f2tf32(pa[s].x); da[1] = f2tf32(pa[s].y);
            da[2] = f2tf32(pa[s].z); da[3] = f2tf32(pa[s].w);
            uint32_t* db = &sB[rowS[s]][qS[s]];
            db[0] = f2tf32(pb[s].x); db[1] = f2tf32(pb[s].y);
            db[2] = f2tf32(pb[s].z); db[3] = f2tf32(pb[s].w);
        }
        __syncthreads();
        if (k0 + 32 < K) {
            const int kn = k0 + 32;
#pragma unroll
            for (int s = 0; s < 4; s++) {
                pa[s] = *(const float4*)(A  + (size_t)gmA[s] * K + kn + qS[s]);
                pb[s] = *(const float4*)(Bt + (size_t)(n0 + rowS[s]) * K + kn + qS[s]);
            }
        }
#pragma unroll
        for (int kk = 0; kk < 32; kk += 8) {
            uint32_t af[4][4], bf[4][2];
#pragma unroll
            for (int mt = 0; mt < 4; mt++) {
                const int r = wm * 64 + mt * 16 + lr;
                af[mt][0] = sA[r][kk + lc];
                af[mt][1] = sA[r + 8][kk + lc];
                af[mt][2] = sA[r][kk + lc + 4];
                af[mt][3] = sA[r + 8][kk + lc + 4];
            }
#pragma unroll
            for (int nt = 0; nt < 4; nt++) {
                const int c = wn * 32 + nt * 8 + lr;
                bf[nt][0] = sB[c][kk + lc];
                bf[nt][1] = sB[c][kk + lc + 4];
            }
#pragma unroll
            for (int mt = 0; mt < 4; mt++)
#pragma unroll
                for (int nt = 0; nt < 4; nt++)
                    mma_tf32(acc[mt][nt], af[mt], bf[nt]);
        }
    }

    // epilogue: c0,c1 at (row lr, cols 2*lc, 2*lc+1); c2,c3 at row lr+8
    const int colq = lc * 2;
#pragma unroll
    for (int mt = 0; mt < 4; mt++) {
        const int row0 = m0 + wm * 64 + mt * 16 + lr;
        const int row1 = row0 + 8;
#pragma unroll
        for (int nt = 0; nt < 4; nt++) {
            const int col = n0 + wn * 32 + nt * 8 + colq;
            const float b0 = bias[col], b1 = bias[col + 1];
            if (BF16OUT) {
                if (row0 < M)
                    *(__nv_bfloat162*)(outH + (size_t)row0 * N + col) =
                        __floats2bfloat162_rn(acc[mt][nt][0] + b0, acc[mt][nt][1] + b1);
                if (row1 < M)
                    *(__nv_bfloat162*)(outH + (size_t)row1 * N + col) =
                        __floats2bfloat162_rn(acc[mt][nt][2] + b0, acc[mt][nt][3] + b1);
            } else {
                if (row0 < M) {
                    float2 v0 = make_float2(acc[mt][nt][0] + b0, acc[mt][nt][1] + b1);
                    *(float2*)(outF + (size_t)row0 * N + col) = v0;
                }
                if (row1 < M) {
                    float2 v1 = make_float2(acc[mt][nt][2] + b0, acc[mt][nt][3] + b1);
                    *(float2*)(outF + (size_t)row1 * N + col) = v1;
                }
            }
        }
    }
}

// ---------------- h-GEMM: [sProj | gh](partials) = h @ Wcat ----------------
__global__ void hgemm_kernel() {
    const int ks = blockIdx.x >> 5;
    const int ct = blockIdx.x & 31;
    const int k0 = ks * 128;
    const int warp = threadIdx.x >> 5;
    const int lane = threadIdx.x & 31;
    const int c = ct * 64 + warp * 4;
    __shared__ float s_h[128 * 32];
    for (int i = threadIdx.x; i < 128 * 32; i += 512)
        s_h[i] = g_hT[k0 * 32 + i];
    __syncthreads();
    float4 acc = make_float4(0.f, 0.f, 0.f, 0.f);
#pragma unroll 8
    for (int kk = 0; kk < 128; kk++) {
        float hv = s_h[kk * 32 + lane];
        float4 wv = *(const float4*)&g_Wcat[(size_t)(k0 + kk) * 2048 + c];
        acc.x += hv * wv.x; acc.y += hv * wv.y;
        acc.z += hv * wv.z; acc.w += hv * wv.w;
    }
    *(float4*)&g_hp[ks][lane][c] = acc;
}

// ---------------- e[b,t] = sum_a tanh(xProj + sProj) * w[a] ----------------
__global__ void e_kernel(const float* __restrict__ sb, const float* __restrict__ wvec) {
    const int b  = blockIdx.y;
    const int t0 = blockIdx.x * 32;
    __shared__ float s_s[512];
    __shared__ float s_w[512];
    for (int i = threadIdx.x; i < 512; i += 256) {
        float s = sb[i];
#pragma unroll
        for (int ks = 0; ks < 4; ks++) s += g_hp[ks][b][i];
        s_s[i] = s;
        s_w[i] = wvec[i];
    }
    __syncthreads();
    const int warp = threadIdx.x >> 5;
    const int lane = threadIdx.x & 31;
    for (int tt = warp; tt < 32; tt += 8) {
        const int t = t0 + tt;
        const uint4* xp = (const uint4*)(g_xProjh + ((size_t)(b * 512 + t)) * 512);
        float acc = 0.f;
#pragma unroll
        for (int it = 0; it < 2; it++) {
            uint4 u = xp[it * 32 + lane];
            const int base = (it * 32 + lane) * 8;
            const unsigned int uu[4] = {u.x, u.y, u.z, u.w};
#pragma unroll
            for (int q = 0; q < 4; q++) {
                float2 v = __bfloat1622float2(*(const __nv_bfloat162*)&uu[q]);
                float a0 = v.x + s_s[base + q * 2];
                float a1 = v.y + s_s[base + q * 2 + 1];
                float t0e = __expf(2.0f * a0);
                float t1e = __expf(2.0f * a1);
                float th0 = 1.0f - __fdividef(2.0f, t0e + 1.0f);
                float th1 = 1.0f - __fdividef(2.0f, t1e + 1.0f);
                acc += th0 * s_w[base + q * 2] + th1 * s_w[base + q * 2 + 1];
            }
        }
#pragma unroll
        for (int off = 16; off; off >>= 1) acc += __shfl_xor_sync(0xffffffffu, acc, off);
        if (lane == 0) g_e[b * 512 + t] = acc;
    }
}

// ---------------- softmax over t + context partials (transposed out) ----------------
__global__ void smctx_kernel(const float* __restrict__ x) {
    const int b  = blockIdx.y;
    const int c  = blockIdx.x;       // 0..7
    const int t0 = c * 64;
    const int tid = threadIdx.x;     // 512
    __shared__ float s_red[512];
    __shared__ float s_alpha[64];

    float v = g_e[b * 512 + tid];
    s_red[tid] = v;
    __syncthreads();
    for (int s = 256; s; s >>= 1) {
        if (tid < s) s_red[tid] = fmaxf(s_red[tid], s_red[tid + s]);
        __syncthreads();
    }
    const float mx = s_red[0];
    __syncthreads();
    s_red[tid] = __expf(v - mx);
    __syncthreads();
    for (int s = 256; s; s >>= 1) {
        if (tid < s) s_red[tid] += s_red[tid + s];
        __syncthreads();
    }
    const float inv = 1.0f / s_red[0];
    if (tid < 64) s_alpha[tid] = __expf(g_e[b * 512 + t0 + tid] - mx) * inv;
    __syncthreads();

    float acc = 0.f;
    const float* xb = x + ((size_t)b * 512 + t0) * 512 + tid;
#pragma unroll 8
    for (int i = 0; i < 64; i++) acc += s_alpha[i] * xb[(size_t)i * 512];
    g_ctxp_t[(c * 512 + tid) * 32 + b] = acc;
}

// ---------------- ctx-GEMM: gi_ctx(partials) = ctx @ Wct ----------------
__global__ void ctxgemm_kernel() {
    const int ct = blockIdx.x;
    const int ks = blockIdx.y;
    const int k0 = ks * 128;
    const int warp = threadIdx.x >> 5;
    const int lane = threadIdx.x & 31;
    const int c = ct * 64 + warp * 4;
    __shared__ float s_h[128 * 32];
    for (int i = threadIdx.x; i < 128 * 32; i += 512) {
        float s = 0.f;
#pragma unroll
        for (int c8 = 0; c8 < 8; c8++) s += g_ctxp_t[c8 * 512 * 32 + k0 * 32 + i];
        s_h[i] = s;
    }
    __syncthreads();
    float4 acc = make_float4(0.f, 0.f, 0.f, 0.f);
#pragma unroll 8
    for (int kk = 0; kk < 128; kk++) {
        float hv = s_h[kk * 32 + lane];
        float4 wv = *(const float4*)&g_Wct[(size_t)(k0 + kk) * 1536 + c];
        acc.x += hv * wv.x; acc.y += hv * wv.y;
        acc.z += hv * wv.z; acc.w += hv * wv.w;
    }
    *(float4*)&g_cp[ks][lane][c] = acc;
}

// ---------------- gates + h update + fc ----------------
__global__ void gates_kernel(const float* __restrict__ fc_w,
                             const float* __restrict__ fc_b,
                             const float* __restrict__ bhh,
                             float* __restrict__ out, int step) {
    const int b = blockIdx.x, j = threadIdx.x;
    __shared__ __align__(16) float s_h[512];

    float ghr = bhh[j], ghz = bhh[512 + j], ghn = bhh[1024 + j];
#pragma unroll
    for (int ks = 0; ks < 4; ks++) {
        ghr += g_hp[ks][b][512 + j];
        ghz += g_hp[ks][b][1024 + j];
        ghn += g_hp[ks][b][1536 + j];
    }
    const float* ge = g_giemb + ((size_t)step * 32 + b) * 1536;
    float gir = ge[j], giz = ge[512 + j], gin = ge[1024 + j];
#pragma unroll
    for (int ks = 0; ks < 4; ks++) {
        gir += g_cp[ks][b][j];
        giz += g_cp[ks][b][512 + j];
        gin += g_cp[ks][b][1024 + j];
    }
    const float r = 1.0f / (1.0f + __expf(-(gir + ghr)));
    const float z = 1.0f / (1.0f + __expf(-(giz + ghz)));
    const float a = gin + r * ghn;
    const float te = __expf(2.0f * a);
    const float n = 1.0f - __fdividef(2.0f, te + 1.0f);
    const float h_old = g_hT[j * 32 + b];
    const float hn = (1.0f - z) * n + z * h_old;
    g_hT[j * 32 + b] = hn;
    s_h[j] = hn;
    __syncthreads();
    if (j < NC) {
        float acc = fc_b[j];
        const float4* wr = (const float4*)(fc_w + j * 512);
        const float4* hh = (const float4*)s_h;
#pragma unroll 8
        for (int k = 0; k < 128; k++) {
            float4 w4 = wr[k];
            float4 h4 = hh[k];
            acc += w4.x * h4.x + w4.y * h4.y + w4.z * h4.z + w4.w * h4.w;
        }
        out[(b * LSTEP + step) * NC + j] = acc;
    }
}

// ---------------- launch ----------------
extern "C" void kernel_launch(void* const* d_in, const int* in_sizes, int n_in,
                              void* d_out, int out_size) {
    const float* x        = (const float*)d_in[0];
    const int*   targets  = (const int*)  d_in[1];
    const float* xEmbed_w = (const float*)d_in[2];
    const float* xEmbed_b = (const float*)d_in[3];
    const float* sEmbed_w = (const float*)d_in[4];
    const float* sEmbed_b = (const float*)d_in[5];
    const float* wEmbed_w = (const float*)d_in[6];
    // d_in[7] = wEmbed_b : constant shift inside softmax -> no-op
    const float* emb      = (const float*)d_in[8];
    const float* gru_wih  = (const float*)d_in[9];
    const float* gru_whh  = (const float*)d_in[10];
    const float* gru_bih  = (const float*)d_in[11];
    const float* gru_bhh  = (const float*)d_in[12];
    const float* fc_w     = (const float*)d_in[13];
    const float* fc_b     = (const float*)d_in[14];
    float* out = (float*)d_out;

    void *p_wxT, *p_weT, *p_embS, *p_giemb, *p_xProjh;
    cudaGetSymbolAddress(&p_wxT, g_wxT);
    cudaGetSymbolAddress(&p_weT, g_weT);
    cudaGetSymbolAddress(&p_embS, g_embS);
    cudaGetSymbolAddress(&p_giemb, g_giemb);
    cudaGetSymbolAddress(&p_xProjh, g_xProjh);

    init_kernel<<<32, 512>>>();
    repack_kernel<<<4096, 256>>>(sEmbed_w, gru_wih, gru_whh);
    wpackx_kernel<<<512, 512>>>(xEmbed_w);
    wpacke_kernel<<<1536, 512>>>(gru_wih);
    embseq_kernel<<<dim3(LSTEP, 32), 512>>>(targets, emb);

    // gi_emb = embSeq @ Wih_emb^T + bih   [800 x 1536], K=512 (TF32 MMA)
    mm_tf32<false><<<dim3(12, 7), 256>>>(
        (const float*)p_embS, (const float*)p_weT, gru_bih,
        (float*)p_giemb, nullptr, LSTEP * 32, 1536, 512);
    // xProj(bf16) = x @ xEmbed_w + b      [16384 x 512], K=512 (TF32 MMA)
    mm_tf32<true><<<dim3(4, 128), 256>>>(
        x, (const float*)p_wxT, xEmbed_b,
        nullptr, (__nv_bfloat16*)p_xProjh, B * T, 512, 512);

    for (int step = 0; step < LSTEP; step++) {
        hgemm_kernel<<<128, 512>>>();
        e_kernel<<<dim3(16, 32), 256>>>(sEmbed_b, wEmbed_w);
        smctx_kernel<<<dim3(8, 32), 512>>>(x);
        ctxgemm_kernel<<<dim3(24, 4), 512>>>();
        gates_kernel<<<32, 512>>>(fc_w, fc_b, gru_bhh, out, step);
    }
}

// round 9
// speedup vs baseline: 2.6313x; 1.0515x over previous
#include <cuda_runtime.h>
#include <cuda_bf16.h>
#include <cstdint>
#include <math.h>

#define B   32
#define T   512
#define XD  512
#define AD  512
#define HD  512
#define NC  97
#define LSTEP 25
#define NBLK 128

// ---------------- device scratch (static, allocation-free) ----------------
__device__ __nv_bfloat16 g_xProjh[B * T * AD];     // bf16 xProj (16.8 MB)
__device__ float g_wxT[512 * 512];                 // xEmbed_w^T  [n][k] fp32
__device__ float g_weT[1536 * 512];                // Wih_emb     [o][k] fp32
__device__ float g_embS[LSTEP * B * 512];          // teacher-forced embeddings fp32
__device__ float g_Wcat[512 * 2048];               // [k][ sEmbed_w(512) | Whh^T(1536) ]
__device__ float g_Wct[512 * 1536];                // Wih_ctx^T   [k][o]
__device__ float g_giemb[LSTEP * B * 1536];        // gi (emb part) + bih
__device__ float g_hT[512 * 32];                   // h transposed [k][b]
__device__ float g_hp[4][32][2048];                // h-GEMM partials
__device__ float g_cp[4][32][1536];                // ctx-GEMM partials
__device__ float g_e[B * T];
__device__ float g_ctxp4[4 * 512 * 32];            // ctx partials [(q*512+d)*32+b]

__device__ unsigned g_cnt = 0;
__device__ unsigned g_gen = 0;

// ---------------- global software barrier ----------------
__device__ __forceinline__ unsigned ld_acq(unsigned* p) {
    unsigned v;
    asm volatile("ld.acquire.gpu.u32 %0, [%1];" : "=r"(v) : "l"(p) : "memory");
    return v;
}
__device__ __forceinline__ void st_rel(unsigned* p, unsigned v) {
    asm volatile("st.release.gpu.u32 [%0], %1;" :: "l"(p), "r"(v) : "memory");
}
__device__ __forceinline__ void gbar() {
    __threadfence();
    __syncthreads();
    if (threadIdx.x == 0) {
        unsigned gen = ld_acq(&g_gen);
        unsigned t = atomicAdd(&g_cnt, 1u);
        if (t == NBLK - 1) {
            g_cnt = 0;
            st_rel(&g_gen, gen + 1);
        } else {
            while (ld_acq(&g_gen) == gen) { }
        }
    }
    __syncthreads();
}

// ---------------- init: h = 0 ----------------
__global__ void init_kernel() {
    g_hT[blockIdx.x * 512 + threadIdx.x] = 0.0f;
}

// ---------------- one-time repacks ----------------
__global__ void repack_kernel(const float* __restrict__ sw,
                              const float* __restrict__ wih,
                              const float* __restrict__ whh) {
    int i = blockIdx.x * blockDim.x + threadIdx.x;
    if (i < 512 * 2048) {
        int k = i >> 11, j = i & 2047;
        g_Wcat[i] = (j < 512) ? sw[k * 512 + j] : whh[(j - 512) * 512 + k];
    }
    if (i < 512 * 1536) {
        int k = i / 1536, o = i - k * 1536;
        g_Wct[i] = wih[o * 1024 + 512 + k];
    }
}

__global__ void wpackx_kernel(const float* __restrict__ w) {
    int k = blockIdx.x, n = threadIdx.x;
    g_wxT[n * 512 + k] = w[k * 512 + n];
}

__global__ void wpacke_kernel(const float* __restrict__ wih) {
    int o = blockIdx.x, k = threadIdx.x;
    g_weT[o * 512 + k] = wih[o * 1024 + k];
}

__global__ void embseq_kernel(const int* __restrict__ targets,
                              const float* __restrict__ emb) {
    const int s = blockIdx.x, b = blockIdx.y;
    const int y = (s == 0) ? NC : targets[b * LSTEP + s - 1];
    g_embS[(s * 32 + b) * 512 + threadIdx.x] = emb[y * 512 + threadIdx.x];
}

// ---------------- TF32 warp-MMA GEMM (prologue, unchanged) ----------------
__device__ __forceinline__ uint32_t f2tf32(float v) {
    uint32_t t;
    asm("cvt.rna.tf32.f32 %0, %1;" : "=r"(t) : "f"(v));
    return t;
}

__device__ __forceinline__ void mma_tf32(float* d, const uint32_t* a, const uint32_t* b) {
    asm volatile(
        "mma.sync.aligned.m16n8k8.row.col.f32.tf32.tf32.f32 "
        "{%0,%1,%2,%3}, {%4,%5,%6,%7}, {%8,%9}, {%0,%1,%2,%3};"
        : "+f"(d[0]), "+f"(d[1]), "+f"(d[2]), "+f"(d[3])
        : "r"(a[0]), "r"(a[1]), "r"(a[2]), "r"(a[3]), "r"(b[0]), "r"(b[1]));
}

template<bool BF16OUT>
__global__ __launch_bounds__(256)
void mm_tf32(const float* __restrict__ A,
             const float* __restrict__ Bt,
             const float* __restrict__ bias,
             float* __restrict__ outF, __nv_bfloat16* __restrict__ outH,
             int M, int N, int K) {
    __shared__ uint32_t sA[128][36];
    __shared__ uint32_t sB[128][36];
    const int tid  = threadIdx.x;
    const int warp = tid >> 5;
    const int lane = tid & 31;
    const int wm = warp >> 2;
    const int wn = warp & 3;
    const int lr = lane >> 2;
    const int lc = lane & 3;
    const int m0 = blockIdx.y * 128;
    const int n0 = blockIdx.x * 128;

    float acc[4][4][4];
#pragma unroll
    for (int i = 0; i < 4; i++)
#pragma unroll
        for (int j = 0; j < 4; j++)
#pragma unroll
            for (int q = 0; q < 4; q++) acc[i][j][q] = 0.0f;

    int rowS[4], qS[4], gmA[4];
#pragma unroll
    for (int s = 0; s < 4; s++) {
        int linear = tid + s * 256;
        rowS[s] = linear >> 3;
        qS[s]   = (linear & 7) * 4;
        int gm = m0 + rowS[s]; if (gm >= M) gm = M - 1;
        gmA[s] = gm;
    }
    float4 pa[4], pb[4];
#pragma unroll
    for (int s = 0; s < 4; s++) {
        pa[s] = *(const float4*)(A  + (size_t)gmA[s] * K + qS[s]);
        pb[s] = *(const float4*)(Bt + (size_t)(n0 + rowS[s]) * K + qS[s]);
    }

    for (int k0 = 0; k0 < K; k0 += 32) {
        __syncthreads();
#pragma unroll
        for (int s = 0; s < 4; s++) {
            uint32_t* da = &sA[rowS[s]][qS[s]];
            da[0] = f2tf32(pa[s].x); da[1] = f2tf32(pa[s].y);
            da[2] = f2tf32(pa[s].z); da[3] = f2tf32(pa[s].w);
            uint32_t* db = &sB[rowS[s]][qS[s]];
            db[0] = f2tf32(pb[s].x); db[1] = f2tf32(pb[s].y);
            db[2] = f2tf32(pb[s].z); db[3] = f2tf32(pb[s].w);
        }
        __syncthreads();
        if (k0 + 32 < K) {
            const int kn = k0 + 32;
#pragma unroll
            for (int s = 0; s < 4; s++) {
                pa[s] = *(const float4*)(A  + (size_t)gmA[s] * K + kn + qS[s]);
                pb[s] = *(const float4*)(Bt + (size_t)(n0 + rowS[s]) * K + kn + qS[s]);
            }
        }
#pragma unroll
        for (int kk = 0; kk < 32; kk += 8) {
            uint32_t af[4][4], bf[4][2];
#pragma unroll
            for (int mt = 0; mt < 4; mt++) {
                const int r = wm * 64 + mt * 16 + lr;
                af[mt][0] = sA[r][kk + lc];
                af[mt][1] = sA[r + 8][kk + lc];
                af[mt][2] = sA[r][kk + lc + 4];
                af[mt][3] = sA[r + 8][kk + lc + 4];
            }
#pragma unroll
            for (int nt = 0; nt < 4; nt++) {
                const int c = wn * 32 + nt * 8 + lr;
                bf[nt][0] = sB[c][kk + lc];
                bf[nt][1] = sB[c][kk + lc + 4];
            }
#pragma unroll
            for (int mt = 0; mt < 4; mt++)
#pragma unroll
                for (int nt = 0; nt < 4; nt++)
                    mma_tf32(acc[mt][nt], af[mt], bf[nt]);
        }
    }

    const int colq = lc * 2;
#pragma unroll
    for (int mt = 0; mt < 4; mt++) {
        const int row0 = m0 + wm * 64 + mt * 16 + lr;
        const int row1 = row0 + 8;
#pragma unroll
        for (int nt = 0; nt < 4; nt++) {
            const int col = n0 + wn * 32 + nt * 8 + colq;
            const float b0 = bias[col], b1 = bias[col + 1];
            if (BF16OUT) {
                if (row0 < M)
                    *(__nv_bfloat162*)(outH + (size_t)row0 * N + col) =
                        __floats2bfloat162_rn(acc[mt][nt][0] + b0, acc[mt][nt][1] + b1);
                if (row1 < M)
                    *(__nv_bfloat162*)(outH + (size_t)row1 * N + col) =
                        __floats2bfloat162_rn(acc[mt][nt][2] + b0, acc[mt][nt][3] + b1);
            } else {
                if (row0 < M) {
                    float2 v0 = make_float2(acc[mt][nt][0] + b0, acc[mt][nt][1] + b1);
                    *(float2*)(outF + (size_t)row0 * N + col) = v0;
                }
                if (row1 < M) {
                    float2 v1 = make_float2(acc[mt][nt][2] + b0, acc[mt][nt][3] + b1);
                    *(float2*)(outF + (size_t)row1 * N + col) = v1;
                }
            }
        }
    }
}

// ---------------- persistent fused step loop: 1 kernel, 128 blocks x 512 ----------------
__global__ __launch_bounds__(512, 1)
void step_persistent(const float* __restrict__ x,
                     const float* __restrict__ sb,
                     const float* __restrict__ wvec,
                     const float* __restrict__ fc_w,
                     const float* __restrict__ fc_b,
                     const float* __restrict__ bhh,
                     float* __restrict__ out) {
    __shared__ float SU[4096];   // 16 KB, unioned across phases
    const int tid  = threadIdx.x;
    const int blk  = blockIdx.x;
    const int warp = tid >> 5;
    const int lane = tid & 31;

    for (int step = 0; step < LSTEP; step++) {
        // ---- P1: hgemm  [sProj | gh] partials = h @ Wcat ----
        {
            const int ks = blk >> 5;
            const int ct = blk & 31;
            const int k0 = ks * 128;
            const int c  = ct * 64 + warp * 4;
            for (int i = tid; i < 4096; i += 512)
                SU[i] = g_hT[k0 * 32 + i];
            __syncthreads();
            float4 acc = make_float4(0.f, 0.f, 0.f, 0.f);
#pragma unroll 8
            for (int kk = 0; kk < 128; kk++) {
                float hv = SU[kk * 32 + lane];
                float4 wv = *(const float4*)&g_Wcat[(size_t)(k0 + kk) * 2048 + c];
                acc.x += hv * wv.x; acc.y += hv * wv.y;
                acc.z += hv * wv.z; acc.w += hv * wv.w;
            }
            *(float4*)&g_hp[ks][lane][c] = acc;
        }
        gbar();

        // ---- P2: e[b,t] = sum_a tanh(xProj + sProj) * w[a] ----
        {
            const int b = blk >> 2;
            const int quarter = blk & 3;
            float* s_s = SU;
            float* s_w = SU + 512;
            {
                float s = sb[tid];
#pragma unroll
                for (int ks = 0; ks < 4; ks++) s += g_hp[ks][b][tid];
                s_s[tid] = s;
                s_w[tid] = wvec[tid];
            }
            __syncthreads();
            const uint4* xpb = (const uint4*)(g_xProjh + (size_t)b * 512 * 512);
            for (int r = 0; r < 8; r++) {
                const int t = quarter * 128 + warp * 8 + r;
                const uint4* xp = xpb + (size_t)t * 64;
                float acc = 0.f;
#pragma unroll
                for (int it = 0; it < 2; it++) {
                    uint4 u = xp[it * 32 + lane];
                    const int base = (it * 32 + lane) * 8;
                    const unsigned uu[4] = {u.x, u.y, u.z, u.w};
#pragma unroll
                    for (int q2 = 0; q2 < 4; q2++) {
                        float2 v = __bfloat1622float2(*(const __nv_bfloat162*)&uu[q2]);
                        float a0 = v.x + s_s[base + q2 * 2];
                        float a1 = v.y + s_s[base + q2 * 2 + 1];
                        float e0 = __expf(2.0f * a0);
                        float e1 = __expf(2.0f * a1);
                        float th0 = 1.0f - __fdividef(2.0f, e0 + 1.0f);
                        float th1 = 1.0f - __fdividef(2.0f, e1 + 1.0f);
                        acc += th0 * s_w[base + q2 * 2] + th1 * s_w[base + q2 * 2 + 1];
                    }
                }
#pragma unroll
                for (int off = 16; off; off >>= 1)
                    acc += __shfl_xor_sync(0xffffffffu, acc, off);
                if (lane == 0) g_e[b * 512 + t] = acc;
            }
        }
        gbar();

        // ---- P3: softmax over t + context partial (128 t rows per block) ----
        {
            const int b = blk >> 2;
            const int q = blk & 3;
            const int t0 = q * 128;
            float* s_red   = SU;
            float* s_alpha = SU + 512;

            float v = g_e[b * 512 + tid];
            s_red[tid] = v;
            __syncthreads();
            for (int s = 256; s; s >>= 1) {
                if (tid < s) s_red[tid] = fmaxf(s_red[tid], s_red[tid + s]);
                __syncthreads();
            }
            const float mx = s_red[0];
            __syncthreads();
            s_red[tid] = __expf(v - mx);
            __syncthreads();
            for (int s = 256; s; s >>= 1) {
                if (tid < s) s_red[tid] += s_red[tid + s];
                __syncthreads();
            }
            const float inv = 1.0f / s_red[0];
            if (tid < 128) s_alpha[tid] = __expf(g_e[b * 512 + t0 + tid] - mx) * inv;
            __syncthreads();

            float acc = 0.f;
            const float* xb = x + ((size_t)(b * 512 + t0)) * 512 + tid;
#pragma unroll 8
            for (int i = 0; i < 128; i++)
                acc += s_alpha[i] * xb[(size_t)i * 512];
            g_ctxp4[(q * 512 + tid) * 32 + b] = acc;
        }
        gbar();

        // ---- P4: ctx-GEMM  gi_ctx partials = ctx @ Wct  (96 active blocks) ----
        if (blk < 96) {
            const int ct = blk >> 2;
            const int ks = blk & 3;
            const int k0 = ks * 128;
            const int c  = ct * 64 + warp * 4;
            const float* cp0 = g_ctxp4 + (size_t)k0 * 32;
            for (int i = tid; i < 4096; i += 512) {
                float s = cp0[i] + cp0[512 * 32 + i]
                        + cp0[2 * 512 * 32 + i] + cp0[3 * 512 * 32 + i];
                SU[i] = s;
            }
            __syncthreads();
            float4 acc = make_float4(0.f, 0.f, 0.f, 0.f);
#pragma unroll 8
            for (int kk = 0; kk < 128; kk++) {
                float hv = SU[kk * 32 + lane];
                float4 wv = *(const float4*)&g_Wct[(size_t)(k0 + kk) * 1536 + c];
                acc.x += hv * wv.x; acc.y += hv * wv.y;
                acc.z += hv * wv.z; acc.w += hv * wv.w;
            }
            *(float4*)&g_cp[ks][lane][c] = acc;
        }
        gbar();

        // ---- P5: gates + h update + fc  (32 active blocks) ----
        if (blk < 32) {
            const int b = blk;
            const int j = tid;
            float ghr = bhh[j], ghz = bhh[512 + j], ghn = bhh[1024 + j];
#pragma unroll
            for (int ks = 0; ks < 4; ks++) {
                ghr += g_hp[ks][b][512 + j];
                ghz += g_hp[ks][b][1024 + j];
                ghn += g_hp[ks][b][1536 + j];
            }
            const float* ge = g_giemb + ((size_t)step * 32 + b) * 1536;
            float gir = ge[j], giz = ge[512 + j], gin = ge[1024 + j];
#pragma unroll
            for (int ks = 0; ks < 4; ks++) {
                gir += g_cp[ks][b][j];
                giz += g_cp[ks][b][512 + j];
                gin += g_cp[ks][b][1024 + j];
            }
            const float r = 1.0f / (1.0f + __expf(-(gir + ghr)));
            const float z = 1.0f / (1.0f + __expf(-(giz + ghz)));
            const float a = gin + r * ghn;
            const float te = __expf(2.0f * a);
            const float n = 1.0f - __fdividef(2.0f, te + 1.0f);
            const float h_old = g_hT[j * 32 + b];
            const float hn = (1.0f - z) * n + z * h_old;
            g_hT[j * 32 + b] = hn;
            SU[j] = hn;
            __syncthreads();
            if (j < NC) {
                float acc = fc_b[j];
                const float4* wr = (const float4*)(fc_w + j * 512);
                const float4* hh = (const float4*)SU;
#pragma unroll 8
                for (int k = 0; k < 128; k++) {
                    float4 w4 = wr[k];
                    float4 h4 = hh[k];
                    acc += w4.x * h4.x + w4.y * h4.y + w4.z * h4.z + w4.w * h4.w;
                }
                out[(b * LSTEP + step) * NC + j] = acc;
            }
        }
        gbar();   // hT ready for next step's P1
    }
}

// ---------------- launch ----------------
extern "C" void kernel_launch(void* const* d_in, const int* in_sizes, int n_in,
                              void* d_out, int out_size) {
    const float* x        = (const float*)d_in[0];
    const int*   targets  = (const int*)  d_in[1];
    const float* xEmbed_w = (const float*)d_in[2];
    const float* xEmbed_b = (const float*)d_in[3];
    const float* sEmbed_w = (const float*)d_in[4];
    const float* sEmbed_b = (const float*)d_in[5];
    const float* wEmbed_w = (const float*)d_in[6];
    // d_in[7] = wEmbed_b : constant shift inside softmax -> no-op
    const float* emb      = (const float*)d_in[8];
    const float* gru_wih  = (const float*)d_in[9];
    const float* gru_whh  = (const float*)d_in[10];
    const float* gru_bih  = (const float*)d_in[11];
    const float* gru_bhh  = (const float*)d_in[12];
    const float* fc_w     = (const float*)d_in[13];
    const float* fc_b     = (const float*)d_in[14];
    float* out = (float*)d_out;

    void *p_wxT, *p_weT, *p_embS, *p_giemb, *p_xProjh;
    cudaGetSymbolAddress(&p_wxT, g_wxT);
    cudaGetSymbolAddress(&p_weT, g_weT);
    cudaGetSymbolAddress(&p_embS, g_embS);
    cudaGetSymbolAddress(&p_giemb, g_giemb);
    cudaGetSymbolAddress(&p_xProjh, g_xProjh);

    init_kernel<<<32, 512>>>();
    repack_kernel<<<4096, 256>>>(sEmbed_w, gru_wih, gru_whh);
    wpackx_kernel<<<512, 512>>>(xEmbed_w);
    wpacke_kernel<<<1536, 512>>>(gru_wih);
    embseq_kernel<<<dim3(LSTEP, 32), 512>>>(targets, emb);

    // gi_emb = embSeq @ Wih_emb^T + bih   [800 x 1536], K=512 (TF32 MMA)
    mm_tf32<false><<<dim3(12, 7), 256>>>(
        (const float*)p_embS, (const float*)p_weT, gru_bih,
        (float*)p_giemb, nullptr, LSTEP * 32, 1536, 512);
    // xProj(bf16) = x @ xEmbed_w + b      [16384 x 512], K=512 (TF32 MMA)
    mm_tf32<true><<<dim3(4, 128), 256>>>(
        x, (const float*)p_wxT, xEmbed_b,
        nullptr, (__nv_bfloat16*)p_xProjh, B * T, 512, 512);

    // fused 25-step decoder loop: one persistent kernel
    step_persistent<<<NBLK, 512>>>(x, sEmbed_b, wEmbed_w, fc_w, fc_b, gru_bhh, out);
}

// round 11
// speedup vs baseline: 2.7011x; 1.0266x over previous
#include <cuda_runtime.h>
#include <cuda_bf16.h>
#include <cstdint>
#include <math.h>

#define B   32
#define T   512
#define XD  512
#define AD  512
#define HD  512
#define NC  97
#define LSTEP 25
#define NBLK 128

// ---------------- device scratch (static, allocation-free) ----------------
__device__ __nv_bfloat16 g_xProjh[B * T * AD];     // bf16 xProj (16.8 MB)
__device__ float g_wxT[512 * 512];                 // xEmbed_w^T  [n][k] fp32
__device__ float g_weT[1536 * 512];                // Wih_emb     [o][k] fp32
__device__ float g_embS[LSTEP * B * 512];          // teacher-forced embeddings fp32
__device__ float g_Wcat[512 * 2048];               // [k][ sEmbed_w(512) | Whh^T(1536) ]
__device__ float g_Wct[512 * 1536];                // Wih_ctx^T   [k][o]
__device__ float g_giemb[LSTEP * B * 1536];        // gi (emb part) + bih
__device__ float g_hT[512 * 32];                   // h transposed [k][b]
__device__ float g_hp[4][32][2048];                // h-GEMM partials
__device__ float g_cp[4][32][1536];                // ctx-GEMM partials
__device__ float g_ctxp4[4 * 512 * 32];            // ctx partials [(q*512+d)*32+b]

__device__ unsigned g_arrive[NBLK];                // per-block arrival flags
__device__ unsigned g_release;                     // release word
__device__ unsigned g_mini[32][4];                 // per-b stats flags
__device__ float2   g_stat[32][4];                 // per-(b,q) softmax (max, sumexp)

// ---------------- acquire/release primitives ----------------
__device__ __forceinline__ unsigned ld_acq(const unsigned* p) {
    unsigned v;
    asm volatile("ld.acquire.gpu.u32 %0, [%1];" : "=r"(v) : "l"(p) : "memory");
    return v;
}
__device__ __forceinline__ void st_rel(unsigned* p, unsigned v) {
    asm volatile("st.release.gpu.u32 [%0], %1;" :: "l"(p), "r"(v) : "memory");
}
__device__ __forceinline__ float ftanh(float x) {
    float r;
    asm("tanh.approx.f32 %0, %1;" : "=f"(r) : "f"(x));
    return r;
}

// contention-free grid barrier: per-block flags + block-0 aggregator
__device__ __forceinline__ void gbar(unsigned epoch) {
    __syncthreads();
    if (blockIdx.x == 0) {
        bool ok;
        do {
            ok = (threadIdx.x > 0 && threadIdx.x < NBLK)
               ? (ld_acq(&g_arrive[threadIdx.x]) >= epoch) : true;
        } while (!__syncthreads_and(ok));
        if (threadIdx.x == 0) st_rel(&g_release, epoch);
    } else {
        if (threadIdx.x == 0) {
            st_rel(&g_arrive[blockIdx.x], epoch);
            while (ld_acq(&g_release) < epoch) { }
        }
        __syncthreads();
    }
}

// ---------------- one fused prep kernel ----------------
__global__ void prep_kernel(const int* __restrict__ targets,
                            const float* __restrict__ emb,
                            const float* __restrict__ sw,
                            const float* __restrict__ wih,
                            const float* __restrict__ whh,
                            const float* __restrict__ xw) {
    const int blk = blockIdx.x, tid = threadIdx.x;
    if (blk < 4096) {
        int i = blk * 256 + tid;
        {   int k = i >> 11, j = i & 2047;
            g_Wcat[i] = (j < 512) ? sw[k * 512 + j] : whh[(j - 512) * 512 + k]; }
        if (i < 512 * 1536) {
            int k = i / 1536, o = i - k * 1536;
            g_Wct[i] = wih[o * 1024 + 512 + k];
        }
    } else if (blk < 4352) {
        // tiled transpose: wxT[n][k] = xw[k][n]
        __shared__ float tile[32][33];
        int tb = blk - 4096;
        int k0 = (tb >> 4) * 32, n0 = (tb & 15) * 32;
        int r = tid >> 5, c = tid & 31;
#pragma unroll
        for (int j = 0; j < 4; j++)
            tile[r + 8 * j][c] = xw[(size_t)(k0 + r + 8 * j) * 512 + n0 + c];
        __syncthreads();
#pragma unroll
        for (int j = 0; j < 4; j++)
            g_wxT[(size_t)(n0 + r + 8 * j) * 512 + k0 + c] = tile[c][r + 8 * j];
    } else if (blk < 5888) {
        int o = blk - 4352;
        g_weT[o * 512 + tid]       = wih[o * 1024 + tid];
        g_weT[o * 512 + tid + 256] = wih[o * 1024 + tid + 256];
    } else if (blk < 6688) {
        int sbi = blk - 5888;                  // s*32 + b
        int s = sbi >> 5, b = sbi & 31;
        int y = (s == 0) ? NC : targets[b * LSTEP + s - 1];
        g_embS[(size_t)sbi * 512 + tid]       = emb[y * 512 + tid];
        g_embS[(size_t)sbi * 512 + tid + 256] = emb[y * 512 + tid + 256];
    } else if (blk < 6752) {
        int i = (blk - 6688) * 256 + tid;
        g_hT[i] = 0.0f;
    } else {
        // reset barrier state (required: graph replays re-enter with epochs from 1)
        if (tid < NBLK) g_arrive[tid] = 0;
        if (tid < 128)  ((unsigned*)g_mini)[tid] = 0;
        if (tid == 0)   g_release = 0;
    }
}

// ---------------- TF32 warp-MMA GEMM (prologue) ----------------
__device__ __forceinline__ uint32_t f2tf32(float v) {
    uint32_t t;
    asm("cvt.rna.tf32.f32 %0, %1;" : "=r"(t) : "f"(v));
    return t;
}

__device__ __forceinline__ void mma_tf32(float* d, const uint32_t* a, const uint32_t* b) {
    asm volatile(
        "mma.sync.aligned.m16n8k8.row.col.f32.tf32.tf32.f32 "
        "{%0,%1,%2,%3}, {%4,%5,%6,%7}, {%8,%9}, {%0,%1,%2,%3};"
        : "+f"(d[0]), "+f"(d[1]), "+f"(d[2]), "+f"(d[3])
        : "r"(a[0]), "r"(a[1]), "r"(a[2]), "r"(a[3]), "r"(b[0]), "r"(b[1]));
}

template<bool BF16OUT>
__global__ __launch_bounds__(256)
void mm_tf32(const float* __restrict__ A,
             const float* __restrict__ Bt,
             const float* __restrict__ bias,
             float* __restrict__ outF, __nv_bfloat16* __restrict__ outH,
             int M, int N, int K) {
    __shared__ uint32_t sA[128][36];
    __shared__ uint32_t sB[128][36];
    const int tid  = threadIdx.x;
    const int warp = tid >> 5;
    const int lane = tid & 31;
    const int wm = warp >> 2;
    const int wn = warp & 3;
    const int lr = lane >> 2;
    const int lc = lane & 3;
    const int m0 = blockIdx.y * 128;
    const int n0 = blockIdx.x * 128;

    float acc[4][4][4];
#pragma unroll
    for (int i = 0; i < 4; i++)
#pragma unroll
        for (int j = 0; j < 4; j++)
#pragma unroll
            for (int q = 0; q < 4; q++) acc[i][j][q] = 0.0f;

    int rowS[4], qS[4], gmA[4];
#pragma unroll
    for (int s = 0; s < 4; s++) {
        int linear = tid + s * 256;
        rowS[s] = linear >> 3;
        qS[s]   = (linear & 7) * 4;
        int gm = m0 + rowS[s]; if (gm >= M) gm = M - 1;
        gmA[s] = gm;
    }
    float4 pa[4], pb[4];
#pragma unroll
    for (int s = 0; s < 4; s++) {
        pa[s] = *(const float4*)(A  + (size_t)gmA[s] * K + qS[s]);
        pb[s] = *(const float4*)(Bt + (size_t)(n0 + rowS[s]) * K + qS[s]);
    }

    for (int k0 = 0; k0 < K; k0 += 32) {
        __syncthreads();
#pragma unroll
        for (int s = 0; s < 4; s++) {
            uint32_t* da = &sA[rowS[s]][qS[s]];
            da[0] = f2tf32(pa[s].x); da[1] = f2tf32(pa[s].y);
            da[2] = f2tf32(pa[s].z); da[3] = f2tf32(pa[s].w);
            uint32_t* db = &sB[rowS[s]][qS[s]];
            db[0] = f2tf32(pb[s].x); db[1] = f2tf32(pb[s].y);
            db[2] = f2tf32(pb[s].z); db[3] = f2tf32(pb[s].w);
        }
        __syncthreads();
        if (k0 + 32 < K) {
            const int kn = k0 + 32;
#pragma unroll
            for (int s = 0; s < 4; s++) {
                pa[s] = *(const float4*)(A  + (size_t)gmA[s] * K + kn + qS[s]);
                pb[s] = *(const float4*)(Bt + (size_t)(n0 + rowS[s]) * K + kn + qS[s]);
            }
        }
#pragma unroll
        for (int kk = 0; kk < 32; kk += 8) {
            uint32_t af[4][4], bf[4][2];
#pragma unroll
            for (int mt = 0; mt < 4; mt++) {
                const int r = wm * 64 + mt * 16 + lr;
                af[mt][0] = sA[r][kk + lc];
                af[mt][1] = sA[r + 8][kk + lc];
                af[mt][2] = sA[r][kk + lc + 4];
                af[mt][3] = sA[r + 8][kk + lc + 4];
            }
#pragma unroll
            for (int nt = 0; nt < 4; nt++) {
                const int c = wn * 32 + nt * 8 + lr;
                bf[nt][0] = sB[c][kk + lc];
                bf[nt][1] = sB[c][kk + lc + 4];
            }
#pragma unroll
            for (int mt = 0; mt < 4; mt++)
#pragma unroll
                for (int nt = 0; nt < 4; nt++)
                    mma_tf32(acc[mt][nt], af[mt], bf[nt]);
        }
    }

    const int colq = lc * 2;
#pragma unroll
    for (int mt = 0; mt < 4; mt++) {
        const int row0 = m0 + wm * 64 + mt * 16 + lr;
        const int row1 = row0 + 8;
#pragma unroll
        for (int nt = 0; nt < 4; nt++) {
            const int col = n0 + wn * 32 + nt * 8 + colq;
            const float b0 = bias[col], b1 = bias[col + 1];
            if (BF16OUT) {
                if (row0 < M)
                    *(__nv_bfloat162*)(outH + (size_t)row0 * N + col) =
                        __floats2bfloat162_rn(acc[mt][nt][0] + b0, acc[mt][nt][1] + b1);
                if (row1 < M)
                    *(__nv_bfloat162*)(outH + (size_t)row1 * N + col) =
                        __floats2bfloat162_rn(acc[mt][nt][2] + b0, acc[mt][nt][3] + b1);
            } else {
                if (row0 < M) {
                    float2 v0 = make_float2(acc[mt][nt][0] + b0, acc[mt][nt][1] + b1);
                    *(float2*)(outF + (size_t)row0 * N + col) = v0;
                }
                if (row1 < M) {
                    float2 v1 = make_float2(acc[mt][nt][2] + b0, acc[mt][nt][3] + b1);
                    *(float2*)(outF + (size_t)row1 * N + col) = v1;
                }
            }
        }
    }
}

// ---------------- persistent fused step loop ----------------
__global__ __launch_bounds__(512, 1)
void step_persistent(const float* __restrict__ x,
                     const float* __restrict__ sb,
                     const float* __restrict__ wvec,
                     const float* __restrict__ fc_w,
                     const float* __restrict__ fc_b,
                     const float* __restrict__ bhh,
                     float* __restrict__ out) {
    __shared__ float SU[4096];     // unioned per phase
    __shared__ float s_w[512];     // wEmbed_w, persistent
    const int tid  = threadIdx.x;
    const int blk  = blockIdx.x;
    const int warp = tid >> 5;
    const int lane = tid & 31;

    s_w[tid] = wvec[tid];
    __syncthreads();

    unsigned epoch = 0;

    for (int step = 0; step < LSTEP; step++) {
        // ---- P1: hgemm  [sProj | gh] partials = h @ Wcat (128 blocks) ----
        {
            const int ks = blk >> 5;
            const int ct = blk & 31;
            const int k0 = ks * 128;
            const int c  = ct * 64 + warp * 4;
            for (int i = tid; i < 4096; i += 512)
                SU[i] = g_hT[k0 * 32 + i];
            __syncthreads();
            float4 acc = make_float4(0.f, 0.f, 0.f, 0.f);
#pragma unroll 8
            for (int kk = 0; kk < 128; kk++) {
                float hv = SU[kk * 32 + lane];
                float4 wv = *(const float4*)&g_Wcat[(size_t)(k0 + kk) * 2048 + c];
                acc.x += hv * wv.x; acc.y += hv * wv.y;
                acc.z += hv * wv.z; acc.w += hv * wv.w;
            }
            *(float4*)&g_hp[ks][lane][c] = acc;
        }
        gbar(++epoch);

        // ---- P2+P3 merged: e, softmax (group sync), ctx partial ----
        {
            const int b = blk >> 2;
            const int q = blk & 3;
            float* s_s   = SU;         // 512: sProj
            float* s_e   = SU + 512;   // 128: local e
            float* s_al  = SU + 640;   // 128: alpha
            float* s_red = SU + 768;   // 8

            float s = sb[tid];
#pragma unroll
            for (int ks = 0; ks < 4; ks++) s += g_hp[ks][b][tid];
            s_s[tid] = s;
            __syncthreads();

            const uint4* xpb = (const uint4*)(g_xProjh + (size_t)b * 512 * 512);
            for (int r = 0; r < 8; r++) {
                const int t = q * 128 + warp * 8 + r;
                const uint4* xp = xpb + (size_t)t * 64;
                float acc = 0.f;
#pragma unroll
                for (int it = 0; it < 2; it++) {
                    uint4 u = xp[it * 32 + lane];
                    const int base = (it * 32 + lane) * 8;
                    const unsigned uu[4] = {u.x, u.y, u.z, u.w};
#pragma unroll
                    for (int q2 = 0; q2 < 4; q2++) {
                        float2 v = __bfloat1622float2(*(const __nv_bfloat162*)&uu[q2]);
                        acc += ftanh(v.x + s_s[base + q2 * 2]) * s_w[base + q2 * 2]
                             + ftanh(v.y + s_s[base + q2 * 2 + 1]) * s_w[base + q2 * 2 + 1];
                    }
                }
#pragma unroll
                for (int off = 16; off; off >>= 1)
                    acc += __shfl_xor_sync(0xffffffffu, acc, off);
                if (lane == 0) s_e[warp * 8 + r] = acc;
            }
            __syncthreads();

            // local max over 128 e's
            float mv = (tid < 128) ? s_e[tid] : -1e30f;
#pragma unroll
            for (int off = 16; off; off >>= 1)
                mv = fmaxf(mv, __shfl_xor_sync(0xffffffffu, mv, off));
            if (tid < 128 && lane == 0) s_red[warp] = mv;
            __syncthreads();
            const float m_loc = fmaxf(fmaxf(s_red[0], s_red[1]),
                                      fmaxf(s_red[2], s_red[3]));
            // local sumexp
            float ev = (tid < 128) ? __expf(s_e[tid] - m_loc) : 0.f;
#pragma unroll
            for (int off = 16; off; off >>= 1)
                ev += __shfl_xor_sync(0xffffffffu, ev, off);
            if (tid < 128 && lane == 0) s_red[4 + warp] = ev;
            __syncthreads();
            if (tid == 0) {
                float s_loc = s_red[4] + s_red[5] + s_red[6] + s_red[7];
                g_stat[b][q] = make_float2(m_loc, s_loc);
                st_rel(&g_mini[b][q], (unsigned)(step + 1));
            }
            // mini-sync among the 4 blocks of this b
            {
                bool ok;
                do {
                    ok = ld_acq(&g_mini[b][tid & 3]) >= (unsigned)(step + 1);
                } while (!__syncthreads_and(ok));
            }
            float2 st0 = g_stat[b][0], st1 = g_stat[b][1];
            float2 st2 = g_stat[b][2], st3 = g_stat[b][3];
            const float M = fmaxf(fmaxf(st0.x, st1.x), fmaxf(st2.x, st3.x));
            const float S = st0.y * __expf(st0.x - M) + st1.y * __expf(st1.x - M)
                          + st2.y * __expf(st2.x - M) + st3.y * __expf(st3.x - M);
            const float invS = 1.0f / S;
            if (tid < 128) s_al[tid] = __expf(s_e[tid] - M) * invS;
            __syncthreads();

            float acc = 0.f;
            const float* xb = x + ((size_t)(b * 512 + q * 128)) * 512 + tid;
#pragma unroll 8
            for (int i = 0; i < 128; i++)
                acc += s_al[i] * xb[(size_t)i * 512];
            g_ctxp4[(q * 512 + tid) * 32 + b] = acc;
        }
        gbar(++epoch);

        // ---- P4: ctx-GEMM gi_ctx partials = ctx @ Wct (96 blocks) ----
        if (blk < 96) {
            const int ct = blk >> 2;
            const int ks = blk & 3;
            const int k0 = ks * 128;
            const int c  = ct * 64 + warp * 4;
            const float* cp0 = g_ctxp4 + (size_t)k0 * 32;
            for (int i = tid; i < 4096; i += 512) {
                SU[i] = cp0[i] + cp0[512 * 32 + i]
                      + cp0[2 * 512 * 32 + i] + cp0[3 * 512 * 32 + i];
            }
            __syncthreads();
            float4 acc = make_float4(0.f, 0.f, 0.f, 0.f);
#pragma unroll 8
            for (int kk = 0; kk < 128; kk++) {
                float hv = SU[kk * 32 + lane];
                float4 wv = *(const float4*)&g_Wct[(size_t)(k0 + kk) * 1536 + c];
                acc.x += hv * wv.x; acc.y += hv * wv.y;
                acc.z += hv * wv.z; acc.w += hv * wv.w;
            }
            *(float4*)&g_cp[ks][lane][c] = acc;
        }
        gbar(++epoch);

        // ---- P5: gates + h update + fc (32 blocks) ----
        if (blk < 32) {
            const int b = blk;
            const int j = tid;
            float ghr = bhh[j], ghz = bhh[512 + j], ghn = bhh[1024 + j];
#pragma unroll
            for (int ks = 0; ks < 4; ks++) {
                ghr += g_hp[ks][b][512 + j];
                ghz += g_hp[ks][b][1024 + j];
                ghn += g_hp[ks][b][1536 + j];
            }
            const float* ge = g_giemb + ((size_t)step * 32 + b) * 1536;
            float gir = ge[j], giz = ge[512 + j], gin = ge[1024 + j];
#pragma unroll
            for (int ks = 0; ks < 4; ks++) {
                gir += g_cp[ks][b][j];
                giz += g_cp[ks][b][512 + j];
                gin += g_cp[ks][b][1024 + j];
            }
            const float r = 1.0f / (1.0f + __expf(-(gir + ghr)));
            const float z = 1.0f / (1.0f + __expf(-(giz + ghz)));
            const float n = ftanh(gin + r * ghn);
            const float h_old = g_hT[j * 32 + b];
            const float hn = (1.0f - z) * n + z * h_old;
            g_hT[j * 32 + b] = hn;
            SU[j] = hn;
            __syncthreads();
            if (j < NC) {
                float acc = fc_b[j];
                const float4* wr = (const float4*)(fc_w + j * 512);
                const float4* hh = (const float4*)SU;
#pragma unroll 8
                for (int k = 0; k < 128; k++) {
                    float4 w4 = wr[k];
                    float4 h4 = hh[k];
                    acc += w4.x * h4.x + w4.y * h4.y + w4.z * h4.z + w4.w * h4.w;
                }
                out[(b * LSTEP + step) * NC + j] = acc;
            }
        }
        gbar(++epoch);   // h ready for next step's P1
    }
}

// ---------------- launch ----------------
extern "C" void kernel_launch(void* const* d_in, const int* in_sizes, int n_in,
                              void* d_out, int out_size) {
    const float* x        = (const float*)d_in[0];
    const int*   targets  = (const int*)  d_in[1];
    const float* xEmbed_w = (const float*)d_in[2];
    const float* xEmbed_b = (const float*)d_in[3];
    const float* sEmbed_w = (const float*)d_in[4];
    const float* sEmbed_b = (const float*)d_in[5];
    const float* wEmbed_w = (const float*)d_in[6];
    // d_in[7] = wEmbed_b : constant shift inside softmax -> no-op
    const float* emb      = (const float*)d_in[8];
    const float* gru_wih  = (const float*)d_in[9];
    const float* gru_whh  = (const float*)d_in[10];
    const float* gru_bih  = (const float*)d_in[11];
    const float* gru_bhh  = (const float*)d_in[12];
    const float* fc_w     = (const float*)d_in[13];
    const float* fc_b     = (const float*)d_in[14];
    float* out = (float*)d_out;

    void *p_wxT, *p_weT, *p_embS, *p_giemb, *p_xProjh;
    cudaGetSymbolAddress(&p_wxT, g_wxT);
    cudaGetSymbolAddress(&p_weT, g_weT);
    cudaGetSymbolAddress(&p_embS, g_embS);
    cudaGetSymbolAddress(&p_giemb, g_giemb);
    cudaGetSymbolAddress(&p_xProjh, g_xProjh);

    // fused prep: repacks + transpose + embseq + h=0 + barrier reset
    prep_kernel<<<6753, 256>>>(targets, emb, sEmbed_w, gru_wih, gru_whh, xEmbed_w);

    // gi_emb = embSeq @ Wih_emb^T + bih   [800 x 1536], K=512 (TF32 MMA)
    mm_tf32<false><<<dim3(12, 7), 256>>>(
        (const float*)p_embS, (const float*)p_weT, gru_bih,
        (float*)p_giemb, nullptr, LSTEP * 32, 1536, 512);
    // xProj(bf16) = x @ xEmbed_w + b      [16384 x 512], K=512 (TF32 MMA)
    mm_tf32<true><<<dim3(4, 128), 256>>>(
        x, (const float*)p_wxT, xEmbed_b,
        nullptr, (__nv_bfloat16*)p_xProjh, B * T, 512, 512);

    // fused 25-step decoder loop: one persistent kernel
    step_persistent<<<NBLK, 512>>>(x, sEmbed_b, wEmbed_w, fc_w, fc_b, gru_bhh, out);
}

// round 13
// speedup vs baseline: 2.9007x; 1.0739x over previous
#include <cuda_runtime.h>
#include <cuda_bf16.h>
#include <cstdint>
#include <math.h>

#define B   32
#define T   512
#define XD  512
#define AD  512
#define HD  512
#define NC  97
#define LSTEP 25
#define NBLK 128

// ---------------- device scratch (static, allocation-free) ----------------
__device__ __nv_bfloat16 g_xProjh[B * T * AD];     // bf16 xProj (16.8 MB)
__device__ float g_wxT[512 * 512];                 // xEmbed_w^T  [n][k] fp32
__device__ float g_weT[1536 * 512];                // Wih_emb     [o][k] fp32
__device__ float g_embS[LSTEP * B * 512];          // teacher-forced embeddings fp32
__device__ float g_Wcat[512 * 2048];               // [k][ sEmbed_w(512) | Whh^T(1536) ]
__device__ float g_Wct[512 * 1536];                // Wih_ctx^T   [k][o]
__device__ float g_giemb[LSTEP * B * 1536];        // gi (emb part) + bih
__device__ float g_hT[512 * 32];                   // h transposed [k][b]
__device__ float g_hp[4][32][2048];                // h-GEMM partials
__device__ float g_cp[4][32][1536];                // ctx-GEMM partials
__device__ float g_ctxp4[4 * 512 * 32];            // ctx partials [(q*512+d)*32+b]

// padded sync flags: 32B stride -> spread across L2 lines; monotone epochs
__device__ unsigned g_arriveP[NBLK * 8];           // arrival flag for block i at [i*8]
__device__ unsigned g_release;                     // release word (block 0 only writer)
__device__ unsigned g_miniP[32 * 4 * 8];           // mini flag (b,q) at [(b*4+q)*8]
__device__ float2   g_stat[32][4];                 // per-(b,q) softmax (max, sumexp)

// ---------------- acquire/release primitives ----------------
__device__ __forceinline__ unsigned ld_acq(const unsigned* p) {
    unsigned v;
    asm volatile("ld.acquire.gpu.u32 %0, [%1];" : "=r"(v) : "l"(p) : "memory");
    return v;
}
__device__ __forceinline__ void st_rel(unsigned* p, unsigned v) {
    asm volatile("st.release.gpu.u32 [%0], %1;" :: "l"(p), "r"(v) : "memory");
}
__device__ __forceinline__ float ftanh(float x) {
    float r;
    asm("tanh.approx.f32 %0, %1;" : "=f"(r) : "f"(x));
    return r;
}

// contention-free grid barrier: per-block padded flags + block-0 aggregator
__device__ __forceinline__ void gbar(unsigned epoch) {
    __syncthreads();
    if (blockIdx.x == 0) {
        bool ok;
        do {
            ok = (threadIdx.x > 0 && threadIdx.x < NBLK)
               ? (ld_acq(&g_arriveP[threadIdx.x * 8]) >= epoch) : true;
        } while (!__syncthreads_and(ok));
        if (threadIdx.x == 0) st_rel(&g_release, epoch);
    } else {
        if (threadIdx.x == 0) {
            st_rel(&g_arriveP[blockIdx.x * 8], epoch);
            while (ld_acq(&g_release) < epoch) { }
        }
        __syncthreads();
    }
}

// ---------------- one fused prep kernel ----------------
__global__ void prep_kernel(const int* __restrict__ targets,
                            const float* __restrict__ emb,
                            const float* __restrict__ sw,
                            const float* __restrict__ wih,
                            const float* __restrict__ whh,
                            const float* __restrict__ xw) {
    const int blk = blockIdx.x, tid = threadIdx.x;
    if (blk < 4096) {
        int i = blk * 256 + tid;
        {   int k = i >> 11, j = i & 2047;
            g_Wcat[i] = (j < 512) ? sw[k * 512 + j] : whh[(j - 512) * 512 + k]; }
        if (i < 512 * 1536) {
            int k = i / 1536, o = i - k * 1536;
            g_Wct[i] = wih[o * 1024 + 512 + k];
        }
    } else if (blk < 4352) {
        // tiled transpose: wxT[n][k] = xw[k][n]
        __shared__ float tile[32][33];
        int tb = blk - 4096;
        int k0 = (tb >> 4) * 32, n0 = (tb & 15) * 32;
        int r = tid >> 5, c = tid & 31;
#pragma unroll
        for (int j = 0; j < 4; j++)
            tile[r + 8 * j][c] = xw[(size_t)(k0 + r + 8 * j) * 512 + n0 + c];
        __syncthreads();
#pragma unroll
        for (int j = 0; j < 4; j++)
            g_wxT[(size_t)(n0 + r + 8 * j) * 512 + k0 + c] = tile[c][r + 8 * j];
    } else if (blk < 5888) {
        int o = blk - 4352;
        g_weT[o * 512 + tid]       = wih[o * 1024 + tid];
        g_weT[o * 512 + tid + 256] = wih[o * 1024 + tid + 256];
    } else if (blk < 6688) {
        int sbi = blk - 5888;                  // s*32 + b
        int s = sbi >> 5, b = sbi & 31;
        int y = (s == 0) ? NC : targets[b * LSTEP + s - 1];
        g_embS[(size_t)sbi * 512 + tid]       = emb[y * 512 + tid];
        g_embS[(size_t)sbi * 512 + tid + 256] = emb[y * 512 + tid + 256];
    } else {
        int i = (blk - 6688) * 256 + tid;
        g_hT[i] = 0.0f;
    }
}

// ---------------- TF32 warp-MMA GEMM (prologue) ----------------
__device__ __forceinline__ uint32_t f2tf32(float v) {
    uint32_t t;
    asm("cvt.rna.tf32.f32 %0, %1;" : "=r"(t) : "f"(v));
    return t;
}

__device__ __forceinline__ void mma_tf32(float* d, const uint32_t* a, const uint32_t* b) {
    asm volatile(
        "mma.sync.aligned.m16n8k8.row.col.f32.tf32.tf32.f32 "
        "{%0,%1,%2,%3}, {%4,%5,%6,%7}, {%8,%9}, {%0,%1,%2,%3};"
        : "+f"(d[0]), "+f"(d[1]), "+f"(d[2]), "+f"(d[3])
        : "r"(a[0]), "r"(a[1]), "r"(a[2]), "r"(a[3]), "r"(b[0]), "r"(b[1]));
}

template<bool BF16OUT>
__global__ __launch_bounds__(256)
void mm_tf32(const float* __restrict__ A,
             const float* __restrict__ Bt,
             const float* __restrict__ bias,
             float* __restrict__ outF, __nv_bfloat16* __restrict__ outH,
             int M, int N, int K) {
    __shared__ uint32_t sA[128][36];
    __shared__ uint32_t sB[128][36];
    const int tid  = threadIdx.x;
    const int warp = tid >> 5;
    const int lane = tid & 31;
    const int wm = warp >> 2;
    const int wn = warp & 3;
    const int lr = lane >> 2;
    const int lc = lane & 3;
    const int m0 = blockIdx.y * 128;
    const int n0 = blockIdx.x * 128;

    float acc[4][4][4];
#pragma unroll
    for (int i = 0; i < 4; i++)
#pragma unroll
        for (int j = 0; j < 4; j++)
#pragma unroll
            for (int q = 0; q < 4; q++) acc[i][j][q] = 0.0f;

    int rowS[4], qS[4], gmA[4];
#pragma unroll
    for (int s = 0; s < 4; s++) {
        int linear = tid + s * 256;
        rowS[s] = linear >> 3;
        qS[s]   = (linear & 7) * 4;
        int gm = m0 + rowS[s]; if (gm >= M) gm = M - 1;
        gmA[s] = gm;
    }
    float4 pa[4], pb[4];
#pragma unroll
    for (int s = 0; s < 4; s++) {
        pa[s] = *(const float4*)(A  + (size_t)gmA[s] * K + qS[s]);
        pb[s] = *(const float4*)(Bt + (size_t)(n0 + rowS[s]) * K + qS[s]);
    }

    for (int k0 = 0; k0 < K; k0 += 32) {
        __syncthreads();
#pragma unroll
        for (int s = 0; s < 4; s++) {
            uint32_t* da = &sA[rowS[s]][qS[s]];
            da[0] = f2tf32(pa[s].x); da[1] = f2tf32(pa[s].y);
            da[2] = f2tf32(pa[s].z); da[3] = f2tf32(pa[s].w);
            uint32_t* db = &sB[rowS[s]][qS[s]];
            db[0] = f2tf32(pb[s].x); db[1] = f2tf32(pb[s].y);
            db[2] = f2tf32(pb[s].z); db[3] = f2tf32(pb[s].w);
        }
        __syncthreads();
        if (k0 + 32 < K) {
            const int kn = k0 + 32;
#pragma unroll
            for (int s = 0; s < 4; s++) {
                pa[s] = *(const float4*)(A  + (size_t)gmA[s] * K + kn + qS[s]);
                pb[s] = *(const float4*)(Bt + (size_t)(n0 + rowS[s]) * K + kn + qS[s]);
            }
        }
#pragma unroll
        for (int kk = 0; kk < 32; kk += 8) {
            uint32_t af[4][4], bf[4][2];
#pragma unroll
            for (int mt = 0; mt < 4; mt++) {
                const int r = wm * 64 + mt * 16 + lr;
                af[mt][0] = sA[r][kk + lc];
                af[mt][1] = sA[r + 8][kk + lc];
                af[mt][2] = sA[r][kk + lc + 4];
                af[mt][3] = sA[r + 8][kk + lc + 4];
            }
#pragma unroll
            for (int nt = 0; nt < 4; nt++) {
                const int c = wn * 32 + nt * 8 + lr;
                bf[nt][0] = sB[c][kk + lc];
                bf[nt][1] = sB[c][kk + lc + 4];
            }
#pragma unroll
            for (int mt = 0; mt < 4; mt++)
#pragma unroll
                for (int nt = 0; nt < 4; nt++)
                    mma_tf32(acc[mt][nt], af[mt], bf[nt]);
        }
    }

    const int colq = lc * 2;
#pragma unroll
    for (int mt = 0; mt < 4; mt++) {
        const int row0 = m0 + wm * 64 + mt * 16 + lr;
        const int row1 = row0 + 8;
#pragma unroll
        for (int nt = 0; nt < 4; nt++) {
            const int col = n0 + wn * 32 + nt * 8 + colq;
            const float b0 = bias[col], b1 = bias[col + 1];
            if (BF16OUT) {
                if (row0 < M)
                    *(__nv_bfloat162*)(outH + (size_t)row0 * N + col) =
                        __floats2bfloat162_rn(acc[mt][nt][0] + b0, acc[mt][nt][1] + b1);
                if (row1 < M)
                    *(__nv_bfloat162*)(outH + (size_t)row1 * N + col) =
                        __floats2bfloat162_rn(acc[mt][nt][2] + b0, acc[mt][nt][3] + b1);
            } else {
                if (row0 < M) {
                    float2 v0 = make_float2(acc[mt][nt][0] + b0, acc[mt][nt][1] + b1);
                    *(float2*)(outF + (size_t)row0 * N + col) = v0;
                }
                if (row1 < M) {
                    float2 v1 = make_float2(acc[mt][nt][2] + b0, acc[mt][nt][3] + b1);
                    *(float2*)(outF + (size_t)row1 * N + col) = v1;
                }
            }
        }
    }
}

// ---------------- persistent fused step loop ----------------
__global__ __launch_bounds__(512, 1)
void step_persistent(const float* __restrict__ x,
                     const float* __restrict__ sb,
                     const float* __restrict__ wvec,
                     const float* __restrict__ fc_w,
                     const float* __restrict__ fc_b,
                     const float* __restrict__ bhh,
                     float* __restrict__ out) {
    __shared__ float SU[4096];     // unioned per phase
    __shared__ float s_w[512];     // wEmbed_w, persistent
    const int tid  = threadIdx.x;
    const int blk  = blockIdx.x;
    const int warp = tid >> 5;
    const int lane = tid & 31;

    s_w[tid] = wvec[tid];

    // monotone epoch bases (replay-safe: no reset needed; values only grow).
    // g_release is quiescent at kernel entry; own mini flag is written only by
    // this block, so reads are race-free. All threads read the same values.
    const unsigned ebase = ld_acq(&g_release);
    const int bb = blk >> 2, qq = blk & 3;
    const unsigned mbase = ld_acq(&g_miniP[(bb * 4 + qq) * 8]);
    unsigned epoch = ebase;
    __syncthreads();

    for (int step = 0; step < LSTEP; step++) {
        // ---- P1: hgemm  [sProj | gh] partials = h @ Wcat (128 blocks) ----
        {
            const int ks = blk >> 5;
            const int ct = blk & 31;
            const int k0 = ks * 128;
            const int c  = ct * 64 + warp * 4;
            for (int i = tid; i < 4096; i += 512)
                SU[i] = g_hT[k0 * 32 + i];
            __syncthreads();
            float4 acc = make_float4(0.f, 0.f, 0.f, 0.f);
#pragma unroll 8
            for (int kk = 0; kk < 128; kk++) {
                float hv = SU[kk * 32 + lane];
                float4 wv = *(const float4*)&g_Wcat[(size_t)(k0 + kk) * 2048 + c];
                acc.x += hv * wv.x; acc.y += hv * wv.y;
                acc.z += hv * wv.z; acc.w += hv * wv.w;
            }
            *(float4*)&g_hp[ks][lane][c] = acc;
        }
        gbar(++epoch);

        // ---- P2+P3 merged: e, softmax (mini group sync), ctx partial ----
        {
            const int b = bb;
            const int q = qq;
            float* s_s   = SU;         // 512: sProj
            float* s_e   = SU + 512;   // 128: local e
            float* s_al  = SU + 640;   // 128: alpha
            float* s_red = SU + 768;   // 8

            float s = sb[tid];
#pragma unroll
            for (int ks = 0; ks < 4; ks++) s += g_hp[ks][b][tid];
            s_s[tid] = s;
            __syncthreads();

            const uint4* xpb = (const uint4*)(g_xProjh + (size_t)b * 512 * 512);
            for (int r = 0; r < 8; r++) {
                const int t = q * 128 + warp * 8 + r;
                const uint4* xp = xpb + (size_t)t * 64;
                float acc = 0.f;
#pragma unroll
                for (int it = 0; it < 2; it++) {
                    uint4 u = xp[it * 32 + lane];
                    const int base = (it * 32 + lane) * 8;
                    const unsigned uu[4] = {u.x, u.y, u.z, u.w};
#pragma unroll
                    for (int q2 = 0; q2 < 4; q2++) {
                        float2 v = __bfloat1622float2(*(const __nv_bfloat162*)&uu[q2]);
                        acc += ftanh(v.x + s_s[base + q2 * 2]) * s_w[base + q2 * 2]
                             + ftanh(v.y + s_s[base + q2 * 2 + 1]) * s_w[base + q2 * 2 + 1];
                    }
                }
#pragma unroll
                for (int off = 16; off; off >>= 1)
                    acc += __shfl_xor_sync(0xffffffffu, acc, off);
                if (lane == 0) s_e[warp * 8 + r] = acc;
            }
            __syncthreads();

            // local max over 128 e's
            float mv = (tid < 128) ? s_e[tid] : -1e30f;
#pragma unroll
            for (int off = 16; off; off >>= 1)
                mv = fmaxf(mv, __shfl_xor_sync(0xffffffffu, mv, off));
            if (tid < 128 && lane == 0) s_red[warp] = mv;
            __syncthreads();
            const float m_loc = fmaxf(fmaxf(s_red[0], s_red[1]),
                                      fmaxf(s_red[2], s_red[3]));
            // local sumexp
            float ev = (tid < 128) ? __expf(s_e[tid] - m_loc) : 0.f;
#pragma unroll
            for (int off = 16; off; off >>= 1)
                ev += __shfl_xor_sync(0xffffffffu, ev, off);
            if (tid < 128 && lane == 0) s_red[4 + warp] = ev;
            __syncthreads();
            const unsigned mtarget = mbase + (unsigned)(step + 1);
            if (tid == 0) {
                float s_loc = s_red[4] + s_red[5] + s_red[6] + s_red[7];
                g_stat[b][q] = make_float2(m_loc, s_loc);
                st_rel(&g_miniP[(b * 4 + q) * 8], mtarget);
            }
            // mini-sync among the 4 blocks of this b: 4 polling threads only
            if (tid < 4) {
                while (ld_acq(&g_miniP[(b * 4 + tid) * 8]) < mtarget) { }
            }
            __syncthreads();
            float2 st0 = g_stat[b][0], st1 = g_stat[b][1];
            float2 st2 = g_stat[b][2], st3 = g_stat[b][3];
            const float M = fmaxf(fmaxf(st0.x, st1.x), fmaxf(st2.x, st3.x));
            const float S = st0.y * __expf(st0.x - M) + st1.y * __expf(st1.x - M)
                          + st2.y * __expf(st2.x - M) + st3.y * __expf(st3.x - M);
            const float invS = 1.0f / S;
            if (tid < 128) s_al[tid] = __expf(s_e[tid] - M) * invS;
            __syncthreads();

            float acc = 0.f;
            const float* xb = x + ((size_t)(b * 512 + q * 128)) * 512 + tid;
#pragma unroll 8
            for (int i = 0; i < 128; i++)
                acc += s_al[i] * xb[(size_t)i * 512];
            g_ctxp4[(q * 512 + tid) * 32 + b] = acc;
        }
        gbar(++epoch);

        // ---- P4: ctx-GEMM gi_ctx partials = ctx @ Wct (96 blocks) ----
        if (blk < 96) {
            const int ct = blk >> 2;
            const int ks = blk & 3;
            const int k0 = ks * 128;
            const int c  = ct * 64 + warp * 4;
            const float* cp0 = g_ctxp4 + (size_t)k0 * 32;
            for (int i = tid; i < 4096; i += 512) {
                SU[i] = cp0[i] + cp0[512 * 32 + i]
                      + cp0[2 * 512 * 32 + i] + cp0[3 * 512 * 32 + i];
            }
            __syncthreads();
            float4 acc = make_float4(0.f, 0.f, 0.f, 0.f);
#pragma unroll 8
            for (int kk = 0; kk < 128; kk++) {
                float hv = SU[kk * 32 + lane];
                float4 wv = *(const float4*)&g_Wct[(size_t)(k0 + kk) * 1536 + c];
                acc.x += hv * wv.x; acc.y += hv * wv.y;
                acc.z += hv * wv.z; acc.w += hv * wv.w;
            }
            *(float4*)&g_cp[ks][lane][c] = acc;
        }
        gbar(++epoch);

        // ---- P5: gates + h update + fc (32 blocks) ----
        if (blk < 32) {
            const int b = blk;
            const int j = tid;
            float ghr = bhh[j], ghz = bhh[512 + j], ghn = bhh[1024 + j];
#pragma unroll
            for (int ks = 0; ks < 4; ks++) {
                ghr += g_hp[ks][b][512 + j];
                ghz += g_hp[ks][b][1024 + j];
                ghn += g_hp[ks][b][1536 + j];
            }
            const float* ge = g_giemb + ((size_t)step * 32 + b) * 1536;
            float gir = ge[j], giz = ge[512 + j], gin = ge[1024 + j];
#pragma unroll
            for (int ks = 0; ks < 4; ks++) {
                gir += g_cp[ks][b][j];
                giz += g_cp[ks][b][512 + j];
                gin += g_cp[ks][b][1024 + j];
            }
            const float r = 1.0f / (1.0f + __expf(-(gir + ghr)));
            const float z = 1.0f / (1.0f + __expf(-(giz + ghz)));
            const float n = ftanh(gin + r * ghn);
            const float h_old = g_hT[j * 32 + b];
            const float hn = (1.0f - z) * n + z * h_old;
            g_hT[j * 32 + b] = hn;
            SU[j] = hn;
            __syncthreads();
            if (j < NC) {
                float acc = fc_b[j];
                const float4* wr = (const float4*)(fc_w + j * 512);
                const float4* hh = (const float4*)SU;
#pragma unroll 8
                for (int k = 0; k < 128; k++) {
                    float4 w4 = wr[k];
                    float4 h4 = hh[k];
                    acc += w4.x * h4.x + w4.y * h4.y + w4.z * h4.z + w4.w * h4.w;
                }
                out[(b * LSTEP + step) * NC + j] = acc;
            }
        }
        gbar(++epoch);   // h ready for next step's P1
    }
}

// ---------------- launch ----------------
extern "C" void kernel_launch(void* const* d_in, const int* in_sizes, int n_in,
                              void* d_out, int out_size) {
    const float* x        = (const float*)d_in[0];
    const int*   targets  = (const int*)  d_in[1];
    const float* xEmbed_w = (const float*)d_in[2];
    const float* xEmbed_b = (const float*)d_in[3];
    const float* sEmbed_w = (const float*)d_in[4];
    const float* sEmbed_b = (const float*)d_in[5];
    const float* wEmbed_w = (const float*)d_in[6];
    // d_in[7] = wEmbed_b : constant shift inside softmax -> no-op
    const float* emb      = (const float*)d_in[8];
    const float* gru_wih  = (const float*)d_in[9];
    const float* gru_whh  = (const float*)d_in[10];
    const float* gru_bih  = (const float*)d_in[11];
    const float* gru_bhh  = (const float*)d_in[12];
    const float* fc_w     = (const float*)d_in[13];
    const float* fc_b     = (const float*)d_in[14];
    float* out = (float*)d_out;

    void *p_wxT, *p_weT, *p_embS, *p_giemb, *p_xProjh;
    cudaGetSymbolAddress(&p_wxT, g_wxT);
    cudaGetSymbolAddress(&p_weT, g_weT);
    cudaGetSymbolAddress(&p_embS, g_embS);
    cudaGetSymbolAddress(&p_giemb, g_giemb);
    cudaGetSymbolAddress(&p_xProjh, g_xProjh);

    // fused prep: repacks + transpose + embseq + h=0
    prep_kernel<<<6752, 256>>>(targets, emb, sEmbed_w, gru_wih, gru_whh, xEmbed_w);

    // gi_emb = embSeq @ Wih_emb^T + bih   [800 x 1536], K=512 (TF32 MMA)
    mm_tf32<false><<<dim3(12, 7), 256>>>(
        (const float*)p_embS, (const float*)p_weT, gru_bih,
        (float*)p_giemb, nullptr, LSTEP * 32, 1536, 512);
    // xProj(bf16) = x @ xEmbed_w + b      [16384 x 512], K=512 (TF32 MMA)
    mm_tf32<true><<<dim3(4, 128), 256>>>(
        x, (const float*)p_wxT, xEmbed_b,
        nullptr, (__nv_bfloat16*)p_xProjh, B * T, 512, 512);

    // fused 25-step decoder loop: one persistent kernel
    step_persistent<<<NBLK, 512>>>(x, sEmbed_b, wEmbed_w, fc_w, fc_b, gru_bhh, out);
}

// round 14
// speedup vs baseline: 2.9013x; 1.0002x over previous
#include <cuda_runtime.h>
#include <cuda_bf16.h>
#include <cstdint>
#include <math.h>

#define B   32
#define T   512
#define XD  512
#define AD  512
#define HD  512
#define NC  97
#define LSTEP 25
#define NBLK 128

// ---------------- device scratch (static, allocation-free) ----------------
__device__ __nv_bfloat16 g_xProjh[B * T * AD];     // bf16 xProj (16.8 MB)
__device__ float g_wxT[512 * 512];                 // xEmbed_w^T  [n][k] fp32
__device__ float g_weT[1536 * 512];                // Wih_emb     [o][k] fp32
__device__ float g_embS[LSTEP * B * 512];          // teacher-forced embeddings fp32
__device__ float g_Wcat[512 * 2048];               // [k][ sEmbed_w(512) | Whh^T(1536) ]
__device__ float g_Wct[512 * 1536];                // Wih_ctx^T   [k][o]
__device__ float g_giemb[LSTEP * B * 1536];        // gi (emb part) + bih
__device__ float g_hT[512 * 32];                   // h transposed [k][b]
__device__ float g_hp[4][32][2048];                // h-GEMM partials
__device__ float g_cp[4][32][1536];                // ctx-GEMM partials
__device__ float g_ctxp4[4 * 512 * 32];            // ctx partials [(q*512+d)*32+b]

// padded sync flags: 32B stride -> spread across L2 lines; monotone epochs
__device__ unsigned g_arriveP[NBLK * 8];           // arrival flag for block i at [i*8]
__device__ unsigned g_release;                     // release word (block 0 only writer)
__device__ unsigned g_miniP[32 * 4 * 8];           // mini flag (b,q) at [(b*4+q)*8]
__device__ float2   g_stat[32][4];                 // per-(b,q) softmax (max, sumexp)

// ---------------- acquire/release primitives ----------------
__device__ __forceinline__ unsigned ld_acq(const unsigned* p) {
    unsigned v;
    asm volatile("ld.acquire.gpu.u32 %0, [%1];" : "=r"(v) : "l"(p) : "memory");
    return v;
}
__device__ __forceinline__ void st_rel(unsigned* p, unsigned v) {
    asm volatile("st.release.gpu.u32 [%0], %1;" :: "l"(p), "r"(v) : "memory");
}
__device__ __forceinline__ float ftanh(float x) {
    float r;
    asm("tanh.approx.f32 %0, %1;" : "=f"(r) : "f"(x));
    return r;
}

// contention-free grid barrier: per-block padded flags + block-0 aggregator
__device__ __forceinline__ void gbar(unsigned epoch) {
    __syncthreads();
    if (blockIdx.x == 0) {
        bool ok;
        do {
            ok = (threadIdx.x > 0 && threadIdx.x < NBLK)
               ? (ld_acq(&g_arriveP[threadIdx.x * 8]) >= epoch) : true;
        } while (!__syncthreads_and(ok));
        if (threadIdx.x == 0) st_rel(&g_release, epoch);
    } else {
        if (threadIdx.x == 0) {
            st_rel(&g_arriveP[blockIdx.x * 8], epoch);
            while (ld_acq(&g_release) < epoch) { }
        }
        __syncthreads();
    }
}

// ---------------- one fused prep kernel ----------------
__global__ void prep_kernel(const int* __restrict__ targets,
                            const float* __restrict__ emb,
                            const float* __restrict__ sw,
                            const float* __restrict__ wih,
                            const float* __restrict__ whh,
                            const float* __restrict__ xw) {
    const int blk = blockIdx.x, tid = threadIdx.x;
    if (blk < 4096) {
        int i = blk * 256 + tid;
        {   int k = i >> 11, j = i & 2047;
            g_Wcat[i] = (j < 512) ? sw[k * 512 + j] : whh[(j - 512) * 512 + k]; }
        if (i < 512 * 1536) {
            int k = i / 1536, o = i - k * 1536;
            g_Wct[i] = wih[o * 1024 + 512 + k];
        }
    } else if (blk < 4352) {
        // tiled transpose: wxT[n][k] = xw[k][n]
        __shared__ float tile[32][33];
        int tb = blk - 4096;
        int k0 = (tb >> 4) * 32, n0 = (tb & 15) * 32;
        int r = tid >> 5, c = tid & 31;
#pragma unroll
        for (int j = 0; j < 4; j++)
            tile[r + 8 * j][c] = xw[(size_t)(k0 + r + 8 * j) * 512 + n0 + c];
        __syncthreads();
#pragma unroll
        for (int j = 0; j < 4; j++)
            g_wxT[(size_t)(n0 + r + 8 * j) * 512 + k0 + c] = tile[c][r + 8 * j];
    } else if (blk < 5888) {
        int o = blk - 4352;
        g_weT[o * 512 + tid]       = wih[o * 1024 + tid];
        g_weT[o * 512 + tid + 256] = wih[o * 1024 + tid + 256];
    } else if (blk < 6688) {
        int sbi = blk - 5888;                  // s*32 + b
        int s = sbi >> 5, b = sbi & 31;
        int y = (s == 0) ? NC : targets[b * LSTEP + s - 1];
        g_embS[(size_t)sbi * 512 + tid]       = emb[y * 512 + tid];
        g_embS[(size_t)sbi * 512 + tid + 256] = emb[y * 512 + tid + 256];
    } else {
        int i = (blk - 6688) * 256 + tid;
        g_hT[i] = 0.0f;
    }
}

// ---------------- TF32 warp-MMA GEMM (prologue) ----------------
__device__ __forceinline__ uint32_t f2tf32(float v) {
    uint32_t t;
    asm("cvt.rna.tf32.f32 %0, %1;" : "=r"(t) : "f"(v));
    return t;
}

__device__ __forceinline__ void mma_tf32(float* d, const uint32_t* a, const uint32_t* b) {
    asm volatile(
        "mma.sync.aligned.m16n8k8.row.col.f32.tf32.tf32.f32 "
        "{%0,%1,%2,%3}, {%4,%5,%6,%7}, {%8,%9}, {%0,%1,%2,%3};"
        : "+f"(d[0]), "+f"(d[1]), "+f"(d[2]), "+f"(d[3])
        : "r"(a[0]), "r"(a[1]), "r"(a[2]), "r"(a[3]), "r"(b[0]), "r"(b[1]));
}

template<bool BF16OUT>
__global__ __launch_bounds__(256)
void mm_tf32(const float* __restrict__ A,
             const float* __restrict__ Bt,
             const float* __restrict__ bias,
             float* __restrict__ outF, __nv_bfloat16* __restrict__ outH,
             int M, int N, int K) {
    __shared__ uint32_t sA[128][36];
    __shared__ uint32_t sB[128][36];
    const int tid  = threadIdx.x;
    const int warp = tid >> 5;
    const int lane = tid & 31;
    const int wm = warp >> 2;
    const int wn = warp & 3;
    const int lr = lane >> 2;
    const int lc = lane & 3;
    const int m0 = blockIdx.y * 128;
    const int n0 = blockIdx.x * 128;

    float acc[4][4][4];
#pragma unroll
    for (int i = 0; i < 4; i++)
#pragma unroll
        for (int j = 0; j < 4; j++)
#pragma unroll
            for (int q = 0; q < 4; q++) acc[i][j][q] = 0.0f;

    int rowS[4], qS[4], gmA[4];
#pragma unroll
    for (int s = 0; s < 4; s++) {
        int linear = tid + s * 256;
        rowS[s] = linear >> 3;
        qS[s]   = (linear & 7) * 4;
        int gm = m0 + rowS[s]; if (gm >= M) gm = M - 1;
        gmA[s] = gm;
    }
    float4 pa[4], pb[4];
#pragma unroll
    for (int s = 0; s < 4; s++) {
        pa[s] = *(const float4*)(A  + (size_t)gmA[s] * K + qS[s]);
        pb[s] = *(const float4*)(Bt + (size_t)(n0 + rowS[s]) * K + qS[s]);
    }

    for (int k0 = 0; k0 < K; k0 += 32) {
        __syncthreads();
#pragma unroll
        for (int s = 0; s < 4; s++) {
            uint32_t* da = &sA[rowS[s]][qS[s]];
            da[0] = f2tf32(pa[s].x); da[1] = f2tf32(pa[s].y);
            da[2] = f2tf32(pa[s].z); da[3] = f2tf32(pa[s].w);
            uint32_t* db = &sB[rowS[s]][qS[s]];
            db[0] = f2tf32(pb[s].x); db[1] = f2tf32(pb[s].y);
            db[2] = f2tf32(pb[s].z); db[3] = f2tf32(pb[s].w);
        }
        __syncthreads();
        if (k0 + 32 < K) {
            const int kn = k0 + 32;
#pragma unroll
            for (int s = 0; s < 4; s++) {
                pa[s] = *(const float4*)(A  + (size_t)gmA[s] * K + kn + qS[s]);
                pb[s] = *(const float4*)(Bt + (size_t)(n0 + rowS[s]) * K + kn + qS[s]);
            }
        }
#pragma unroll
        for (int kk = 0; kk < 32; kk += 8) {
            uint32_t af[4][4], bf[4][2];
#pragma unroll
            for (int mt = 0; mt < 4; mt++) {
                const int r = wm * 64 + mt * 16 + lr;
                af[mt][0] = sA[r][kk + lc];
                af[mt][1] = sA[r + 8][kk + lc];
                af[mt][2] = sA[r][kk + lc + 4];
                af[mt][3] = sA[r + 8][kk + lc + 4];
            }
#pragma unroll
            for (int nt = 0; nt < 4; nt++) {
                const int c = wn * 32 + nt * 8 + lr;
                bf[nt][0] = sB[c][kk + lc];
                bf[nt][1] = sB[c][kk + lc + 4];
            }
#pragma unroll
            for (int mt = 0; mt < 4; mt++)
#pragma unroll
                for (int nt = 0; nt < 4; nt++)
                    mma_tf32(acc[mt][nt], af[mt], bf[nt]);
        }
    }

    const int colq = lc * 2;
#pragma unroll
    for (int mt = 0; mt < 4; mt++) {
        const int row0 = m0 + wm * 64 + mt * 16 + lr;
        const int row1 = row0 + 8;
#pragma unroll
        for (int nt = 0; nt < 4; nt++) {
            const int col = n0 + wn * 32 + nt * 8 + colq;
            const float b0 = bias[col], b1 = bias[col + 1];
            if (BF16OUT) {
                if (row0 < M)
                    *(__nv_bfloat162*)(outH + (size_t)row0 * N + col) =
                        __floats2bfloat162_rn(acc[mt][nt][0] + b0, acc[mt][nt][1] + b1);
                if (row1 < M)
                    *(__nv_bfloat162*)(outH + (size_t)row1 * N + col) =
                        __floats2bfloat162_rn(acc[mt][nt][2] + b0, acc[mt][nt][3] + b1);
            } else {
                if (row0 < M) {
                    float2 v0 = make_float2(acc[mt][nt][0] + b0, acc[mt][nt][1] + b1);
                    *(float2*)(outF + (size_t)row0 * N + col) = v0;
                }
                if (row1 < M) {
                    float2 v1 = make_float2(acc[mt][nt][2] + b0, acc[mt][nt][3] + b1);
                    *(float2*)(outF + (size_t)row1 * N + col) = v1;
                }
            }
        }
    }
}

// ---------------- persistent fused step loop ----------------
__global__ __launch_bounds__(512, 1)
void step_persistent(const float* __restrict__ x,
                     const float* __restrict__ sb,
                     const float* __restrict__ wvec,
                     const float* __restrict__ fc_w,
                     const float* __restrict__ fc_b,
                     const float* __restrict__ bhh,
                     float* __restrict__ out) {
    __shared__ float SU[4096];     // unioned per phase
    __shared__ float s_w[512];     // wEmbed_w, persistent
    const int tid  = threadIdx.x;
    const int blk  = blockIdx.x;
    const int warp = tid >> 5;
    const int lane = tid & 31;

    s_w[tid] = wvec[tid];

    // monotone epoch bases (replay-safe: no reset needed; values only grow).
    // g_release is quiescent at kernel entry; own mini flag is written only by
    // this block, so reads are race-free. All threads read the same values.
    const unsigned ebase = ld_acq(&g_release);
    const int bb = blk >> 2, qq = blk & 3;
    const unsigned mbase = ld_acq(&g_miniP[(bb * 4 + qq) * 8]);
    unsigned epoch = ebase;
    __syncthreads();

    for (int step = 0; step < LSTEP; step++) {
        // ---- P1: hgemm  [sProj | gh] partials = h @ Wcat (128 blocks) ----
        {
            const int ks = blk >> 5;
            const int ct = blk & 31;
            const int k0 = ks * 128;
            const int c  = ct * 64 + warp * 4;
            for (int i = tid; i < 4096; i += 512)
                SU[i] = g_hT[k0 * 32 + i];
            __syncthreads();
            float4 acc = make_float4(0.f, 0.f, 0.f, 0.f);
#pragma unroll 8
            for (int kk = 0; kk < 128; kk++) {
                float hv = SU[kk * 32 + lane];
                float4 wv = *(const float4*)&g_Wcat[(size_t)(k0 + kk) * 2048 + c];
                acc.x += hv * wv.x; acc.y += hv * wv.y;
                acc.z += hv * wv.z; acc.w += hv * wv.w;
            }
            *(float4*)&g_hp[ks][lane][c] = acc;
        }
        gbar(++epoch);

        // ---- P2+P3 merged: e, softmax (mini group sync), ctx partial ----
        {
            const int b = bb;
            const int q = qq;
            float* s_s   = SU;         // 512: sProj
            float* s_e   = SU + 512;   // 128: local e
            float* s_al  = SU + 640;   // 128: alpha
            float* s_red = SU + 768;   // 8

            float s = sb[tid];
#pragma unroll
            for (int ks = 0; ks < 4; ks++) s += g_hp[ks][b][tid];
            s_s[tid] = s;
            __syncthreads();

            const uint4* xpb = (const uint4*)(g_xProjh + (size_t)b * 512 * 512);
            for (int r = 0; r < 8; r++) {
                const int t = q * 128 + warp * 8 + r;
                const uint4* xp = xpb + (size_t)t * 64;
                float acc = 0.f;
#pragma unroll
                for (int it = 0; it < 2; it++) {
                    uint4 u = xp[it * 32 + lane];
                    const int base = (it * 32 + lane) * 8;
                    const unsigned uu[4] = {u.x, u.y, u.z, u.w};
#pragma unroll
                    for (int q2 = 0; q2 < 4; q2++) {
                        float2 v = __bfloat1622float2(*(const __nv_bfloat162*)&uu[q2]);
                        acc += ftanh(v.x + s_s[base + q2 * 2]) * s_w[base + q2 * 2]
                             + ftanh(v.y + s_s[base + q2 * 2 + 1]) * s_w[base + q2 * 2 + 1];
                    }
                }
#pragma unroll
                for (int off = 16; off; off >>= 1)
                    acc += __shfl_xor_sync(0xffffffffu, acc, off);
                if (lane == 0) s_e[warp * 8 + r] = acc;
            }
            __syncthreads();

            // local max over 128 e's
            float mv = (tid < 128) ? s_e[tid] : -1e30f;
#pragma unroll
            for (int off = 16; off; off >>= 1)
                mv = fmaxf(mv, __shfl_xor_sync(0xffffffffu, mv, off));
            if (tid < 128 && lane == 0) s_red[warp] = mv;
            __syncthreads();
            const float m_loc = fmaxf(fmaxf(s_red[0], s_red[1]),
                                      fmaxf(s_red[2], s_red[3]));
            // local sumexp
            float ev = (tid < 128) ? __expf(s_e[tid] - m_loc) : 0.f;
#pragma unroll
            for (int off = 16; off; off >>= 1)
                ev += __shfl_xor_sync(0xffffffffu, ev, off);
            if (tid < 128 && lane == 0) s_red[4 + warp] = ev;
            __syncthreads();
            const unsigned mtarget = mbase + (unsigned)(step + 1);
            if (tid == 0) {
                float s_loc = s_red[4] + s_red[5] + s_red[6] + s_red[7];
                g_stat[b][q] = make_float2(m_loc, s_loc);
                st_rel(&g_miniP[(b * 4 + q) * 8], mtarget);
            }
            // mini-sync among the 4 blocks of this b: 4 polling threads only
            if (tid < 4) {
                while (ld_acq(&g_miniP[(b * 4 + tid) * 8]) < mtarget) { }
            }
            __syncthreads();
            float2 st0 = g_stat[b][0], st1 = g_stat[b][1];
            float2 st2 = g_stat[b][2], st3 = g_stat[b][3];
            const float M = fmaxf(fmaxf(st0.x, st1.x), fmaxf(st2.x, st3.x));
            const float S = st0.y * __expf(st0.x - M) + st1.y * __expf(st1.x - M)
                          + st2.y * __expf(st2.x - M) + st3.y * __expf(st3.x - M);
            const float invS = 1.0f / S;
            if (tid < 128) s_al[tid] = __expf(s_e[tid] - M) * invS;
            __syncthreads();

            float acc = 0.f;
            const float* xb = x + ((size_t)(b * 512 + q * 128)) * 512 + tid;
#pragma unroll 8
            for (int i = 0; i < 128; i++)
                acc += s_al[i] * xb[(size_t)i * 512];
            g_ctxp4[(q * 512 + tid) * 32 + b] = acc;
        }
        gbar(++epoch);

        // ---- P4: ctx-GEMM gi_ctx partials = ctx @ Wct (96 blocks) ----
        if (blk < 96) {
            const int ct = blk >> 2;
            const int ks = blk & 3;
            const int k0 = ks * 128;
            const int c  = ct * 64 + warp * 4;
            const float* cp0 = g_ctxp4 + (size_t)k0 * 32;
            for (int i = tid; i < 4096; i += 512) {
                SU[i] = cp0[i] + cp0[512 * 32 + i]
                      + cp0[2 * 512 * 32 + i] + cp0[3 * 512 * 32 + i];
            }
            __syncthreads();
            float4 acc = make_float4(0.f, 0.f, 0.f, 0.f);
#pragma unroll 8
            for (int kk = 0; kk < 128; kk++) {
                float hv = SU[kk * 32 + lane];
                float4 wv = *(const float4*)&g_Wct[(size_t)(k0 + kk) * 1536 + c];
                acc.x += hv * wv.x; acc.y += hv * wv.y;
                acc.z += hv * wv.z; acc.w += hv * wv.w;
            }
            *(float4*)&g_cp[ks][lane][c] = acc;
        }
        gbar(++epoch);

        // ---- P5: gates + h update + fc (32 blocks) ----
        if (blk < 32) {
            const int b = blk;
            const int j = tid;
            float ghr = bhh[j], ghz = bhh[512 + j], ghn = bhh[1024 + j];
#pragma unroll
            for (int ks = 0; ks < 4; ks++) {
                ghr += g_hp[ks][b][512 + j];
                ghz += g_hp[ks][b][1024 + j];
                ghn += g_hp[ks][b][1536 + j];
            }
            const float* ge = g_giemb + ((size_t)step * 32 + b) * 1536;
            float gir = ge[j], giz = ge[512 + j], gin = ge[1024 + j];
#pragma unroll
            for (int ks = 0; ks < 4; ks++) {
                gir += g_cp[ks][b][j];
                giz += g_cp[ks][b][512 + j];
                gin += g_cp[ks][b][1024 + j];
            }
            const float r = 1.0f / (1.0f + __expf(-(gir + ghr)));
            const float z = 1.0f / (1.0f + __expf(-(giz + ghz)));
            const float n = ftanh(gin + r * ghn);
            const float h_old = g_hT[j * 32 + b];
            const float hn = (1.0f - z) * n + z * h_old;
            g_hT[j * 32 + b] = hn;
            SU[j] = hn;
            __syncthreads();
            if (j < NC) {
                float acc = fc_b[j];
                const float4* wr = (const float4*)(fc_w + j * 512);
                const float4* hh = (const float4*)SU;
#pragma unroll 8
                for (int k = 0; k < 128; k++) {
                    float4 w4 = wr[k];
                    float4 h4 = hh[k];
                    acc += w4.x * h4.x + w4.y * h4.y + w4.z * h4.z + w4.w * h4.w;
                }
                out[(b * LSTEP + step) * NC + j] = acc;
            }
        }
        gbar(++epoch);   // h ready for next step's P1
    }
}

// ---------------- launch ----------------
extern "C" void kernel_launch(void* const* d_in, const int* in_sizes, int n_in,
                              void* d_out, int out_size) {
    const float* x        = (const float*)d_in[0];
    const int*   targets  = (const int*)  d_in[1];
    const float* xEmbed_w = (const float*)d_in[2];
    const float* xEmbed_b = (const float*)d_in[3];
    const float* sEmbed_w = (const float*)d_in[4];
    const float* sEmbed_b = (const float*)d_in[5];
    const float* wEmbed_w = (const float*)d_in[6];
    // d_in[7] = wEmbed_b : constant shift inside softmax -> no-op
    const float* emb      = (const float*)d_in[8];
    const float* gru_wih  = (const float*)d_in[9];
    const float* gru_whh  = (const float*)d_in[10];
    const float* gru_bih  = (const float*)d_in[11];
    const float* gru_bhh  = (const float*)d_in[12];
    const float* fc_w     = (const float*)d_in[13];
    const float* fc_b     = (const float*)d_in[14];
    float* out = (float*)d_out;

    void *p_wxT, *p_weT, *p_embS, *p_giemb, *p_xProjh;
    cudaGetSymbolAddress(&p_wxT, g_wxT);
    cudaGetSymbolAddress(&p_weT, g_weT);
    cudaGetSymbolAddress(&p_embS, g_embS);
    cudaGetSymbolAddress(&p_giemb, g_giemb);
    cudaGetSymbolAddress(&p_xProjh, g_xProjh);

    // fused prep: repacks + transpose + embseq + h=0
    prep_kernel<<<6752, 256>>>(targets, emb, sEmbed_w, gru_wih, gru_whh, xEmbed_w);

    // gi_emb = embSeq @ Wih_emb^T + bih   [800 x 1536], K=512 (TF32 MMA)
    mm_tf32<false><<<dim3(12, 7), 256>>>(
        (const float*)p_embS, (const float*)p_weT, gru_bih,
        (float*)p_giemb, nullptr, LSTEP * 32, 1536, 512);
    // xProj(bf16) = x @ xEmbed_w + b      [16384 x 512], K=512 (TF32 MMA)
    mm_tf32<true><<<dim3(4, 128), 256>>>(
        x, (const float*)p_wxT, xEmbed_b,
        nullptr, (__nv_bfloat16*)p_xProjh, B * T, 512, 512);

    // fused 25-step decoder loop: one persistent kernel
    step_persistent<<<NBLK, 512>>>(x, sEmbed_b, wEmbed_w, fc_w, fc_b, gru_bhh, out);
}